// round 14
// baseline (speedup 1.0000x reference)
#include <cuda_runtime.h>
#include <cuda_bf16.h>
#include <math.h>

// Problem constants
#define Bsz   2
#define Ssz   1024
#define Dsz   512
#define Hsz   8
#define Vsz   32000
#define DFFsz 2048
#define KS    10     // split-K factor for ex_wte GEMM (32000/10=3200, 3200/64=50)
#define CSCH  16     // chunks for column-sum of R
#define CMCH  128    // chunks for column-mean of wte

typedef long long ll;

// ---------------- device scratch (no allocations allowed) ----------------
__device__ float d_e  [Bsz*Ssz*Dsz];
__device__ float d_p  [(Ssz+1)*Dsz];
__device__ float d_Aq [Hsz*Ssz*Dsz];
__device__ float d_Bk [Hsz*Ssz*Dsz];
__device__ float d_krn[(size_t)Hsz*Ssz*Ssz];
__device__ float d_fk [Bsz*Ssz*Dsz];
__device__ float d_Vt [Bsz*Ssz*Dsz];
__device__ float d_attn[(size_t)Bsz*Ssz*Hsz*Dsz];
__device__ float d_hln[Bsz*Ssz*Dsz];
__device__ float d_act[Bsz*Ssz*DFFsz];
__device__ __nv_bfloat16 d_R[(size_t)Bsz*Vsz*Ssz];   // 131 MB (bf16)
__device__ __nv_bfloat16 d_wteh[(size_t)Vsz*Dsz];    // 33 MB  (bf16 wte)
__device__ __nv_bfloat16 d_fkh[Bsz*Ssz*Dsz];         // 4 MB   (bf16 fk)
__device__ float d_exP[(size_t)Bsz*KS*Ssz*Dsz];
__device__ float d_rsP[CSCH*Bsz*Ssz];
__device__ float d_cmP[CMCH*Dsz];
__device__ float d_cm [Dsz];
__device__ float d_oln[Bsz*Dsz];

enum { EPI_STORE=0, EPI_ADD=1, EPI_GELU=2, EPI_KRN=3 };

// ---------------- ldmatrix / mma wrappers ----------------
__device__ __forceinline__ void ldsm4(unsigned &r0,unsigned &r1,unsigned &r2,unsigned &r3,unsigned a){
    asm volatile("ldmatrix.sync.aligned.m8n8.x4.shared.b16 {%0,%1,%2,%3},[%4];"
        :"=r"(r0),"=r"(r1),"=r"(r2),"=r"(r3):"r"(a));
}
__device__ __forceinline__ void ldsm4t(unsigned &r0,unsigned &r1,unsigned &r2,unsigned &r3,unsigned a){
    asm volatile("ldmatrix.sync.aligned.m8n8.x4.trans.shared.b16 {%0,%1,%2,%3},[%4];"
        :"=r"(r0),"=r"(r1),"=r"(r2),"=r"(r3):"r"(a));
}
__device__ __forceinline__ void ldsm2(unsigned &r0,unsigned &r1,unsigned a){
    asm volatile("ldmatrix.sync.aligned.m8n8.x2.shared.b16 {%0,%1},[%2];"
        :"=r"(r0),"=r"(r1):"r"(a));
}
__device__ __forceinline__ void ldsm2t(unsigned &r0,unsigned &r1,unsigned a){
    asm volatile("ldmatrix.sync.aligned.m8n8.x2.trans.shared.b16 {%0,%1},[%2];"
        :"=r"(r0),"=r"(r1):"r"(a));
}
__device__ __forceinline__ void mma16816(float* c,const unsigned* a,const unsigned* b){
    asm volatile("mma.sync.aligned.m16n8k16.row.col.f32.bf16.bf16.f32 "
        "{%0,%1,%2,%3},{%4,%5,%6,%7},{%8,%9},{%0,%1,%2,%3};"
        : "+f"(c[0]),"+f"(c[1]),"+f"(c[2]),"+f"(c[3])
        : "r"(a[0]),"r"(a[1]),"r"(a[2]),"r"(a[3]),"r"(b[0]),"r"(b[1]));
}

// dynamic smem bytes: 2 stages x ((1+SA)*A + (1+SB)*B) bf16 tiles
template<bool TA,bool TB,int SA,int SB,int BKT> constexpr int smem_bytes(){
    constexpr int ASZ=(TA?BKT:128)*(TA?136:BKT+8);
    constexpr int BSZ=(TB?128:BKT)*(TB?BKT+8:136);
    return 2*((1+SA)*ASZ+(1+SB)*BSZ)*2;
}

// ---------------- bf16 tensor-core GEMM, tiered precision, double-buffered ----
// C(MxN)=A(MxK)*B(KxN). TA: A stored KxM. TB: B stored NxK.
// SA/SB: operand split x=hi+lo (bf16 each). Products: Ah*Bh [+ Ah*Bl if SB]
// [+ Al*Bh if SA], fp32 accum. ABF/BBF: operand already bf16 in gmem (raw copy
// staging, forces that split off). CBF: C written bf16.
// Batched via blockIdx.z (z1=z/Z2, z2=z%Z2). Ksplit>1: z2 picks K-slice.
// triK: kend=min(kend,m0+BM) (causal contraction). 256 thr = 8 warps (2Mx4N).
template<bool TA,bool TB,int SA,int SB,bool ABF,bool BBF,bool CBF,int EPI,int BKT>
__global__ void __launch_bounds__(256,1)
mma_k(int M,int N,int K,
      const void* __restrict__ Av,const void* __restrict__ Bv,void* __restrict__ Cv,
      int lda,int ldb,int ldc,
      int Z2, ll sA1, ll sA2, ll sB1, ll sB2, ll sC1, ll sC2,
      int Ksplit, int triK, float p0)
{
    constexpr int BM=128, BN=128, BK=BKT;
    constexpr int ACols = TA ? BM+8 : BK+8;
    constexpr int BCols = TB ? BK+8 : BN+8;
    constexpr int ARows = TA ? BK : BM;
    constexpr int BRows = TB ? BN : BK;
    constexpr int ASZ = ARows*ACols;
    constexpr int BSZ = BRows*BCols;
    constexpr int STG = (1+SA)*ASZ + (1+SB)*BSZ;   // elems per stage
    constexpr int NAF = BM*BK/1024;   // float4 passes for A (256 thr)
    constexpr int NAB = BM*BK/2048;   // uint4  passes for A
    constexpr int NBF = BN*BK/1024;
    constexpr int NBB = BN*BK/2048;

    extern __shared__ __align__(16) __nv_bfloat16 S[];

    const int z=blockIdx.z, z1=z/Z2, z2=z%Z2;
    const float*         Af=(const float*)Av + z1*sA1 + z2*sA2;
    const __nv_bfloat16* Ab=(const __nv_bfloat16*)Av + z1*sA1 + z2*sA2;
    const float*         Bf=(const float*)Bv + z1*sB1 + z2*sB2;
    const __nv_bfloat16* Bb=(const __nv_bfloat16*)Bv + z1*sB1 + z2*sB2;
    float*         Cf=(float*)Cv + z1*sC1 + z2*sC2;
    __nv_bfloat16* Cb=(__nv_bfloat16*)Cv + z1*sC1 + z2*sC2;
    const int m0=blockIdx.y*BM, n0=blockIdx.x*BN;

    int kbeg=0, kend=K;
    if (Ksplit>1){ int kc=K/Ksplit; kbeg=z2*kc; kend=kbeg+kc; }
    if (triK && kend > m0+BM) kend = m0+BM;
    if (EPI==EPI_KRN && n0 >= m0+BM) kend = kbeg;   // fully masked tile: skip mainloop

    const int tid=threadIdx.x;
    const int lane=tid&31, wid=tid>>5;
    const int wm=wid&1, wn=wid>>1;
    const int gid=lane>>2, tig=lane&3;

    // ldmatrix per-lane offset components
    int a_m, a_k;
    if(!TA){ a_m=(lane&7)+((lane&8)?8:0); a_k=(lane&16)?8:0; }
    else   { a_k=(lane&7)+((lane&16)?8:0); a_m=(lane&8)?8:0; }
    const int l16=lane&15;
    int b_n, b_k;
    if(TB){ b_n=l16&7;                 b_k=(l16&8)?8:0; }
    else  { b_k=(l16&7)+((l16&8)?8:0); b_n=0; }

    const unsigned sbase=(unsigned)__cvta_generic_to_shared(S);

    float acc[4][4][4];
    #pragma unroll
    for(int i=0;i<4;i++)
        #pragma unroll
        for(int j=0;j<4;j++)
            #pragma unroll
            for(int r=0;r<4;r++) acc[i][j][r]=0.f;

    float4 ra[ABF?1:NAF]; uint4 rab[ABF?NAB:1];
    float4 rb[BBF?1:NBF]; uint4 rbb[BBF?NBB:1];

    // ---- staged-load helpers ----
    auto load_regs=[&](int kk0){
        if(ABF){
            #pragma unroll
            for(int u=0;u<NAB;u++){
                int t=tid+u*256;
                if(TA){ int kk=t/(BM/8), mq=(t%(BM/8))*8; rab[u]=*(const uint4*)(Ab+(size_t)(kk0+kk)*lda+m0+mq); }
                else  { int row=t/(BK/8), kq=(t%(BK/8))*8; rab[u]=*(const uint4*)(Ab+(size_t)(m0+row)*lda+kk0+kq); }
            }
        }else{
            #pragma unroll
            for(int u=0;u<NAF;u++){
                int t=tid+u*256;
                if(!TA){ int row=t/(BK/4), kq=(t%(BK/4))*4; ra[u]=*(const float4*)(Af+(size_t)(m0+row)*lda+kk0+kq); }
                else   { int kk=t/(BM/4), mq=(t%(BM/4))*4; ra[u]=*(const float4*)(Af+(size_t)(kk0+kk)*lda+m0+mq); }
            }
        }
        if(BBF){
            #pragma unroll
            for(int u=0;u<NBB;u++){
                int t=tid+u*256;
                if(TB){ int row=t/(BK/8), kq=(t%(BK/8))*8; rbb[u]=*(const uint4*)(Bb+(size_t)(n0+row)*ldb+kk0+kq); }
                else  { int kk=t/(BN/8), nq=(t%(BN/8))*8; rbb[u]=*(const uint4*)(Bb+(size_t)(kk0+kk)*ldb+n0+nq); }
            }
        }else{
            #pragma unroll
            for(int u=0;u<NBF;u++){
                int t=tid+u*256;
                if(TB) { int row=t/(BK/4), kq=(t%(BK/4))*4; rb[u]=*(const float4*)(Bf+(size_t)(n0+row)*ldb+kk0+kq); }
                else   { int kk=t/(BN/4), nq=(t%(BN/4))*4; rb[u]=*(const float4*)(Bf+(size_t)(kk0+kk)*ldb+n0+nq); }
            }
        }
    };
    auto store_stage=[&](int s){
        __nv_bfloat16* Ah = S + s*STG;
        __nv_bfloat16* Al = Ah + ASZ;                  // valid iff SA
        __nv_bfloat16* Bh = Ah + (1+SA)*ASZ;
        __nv_bfloat16* Bl = Bh + BSZ;                  // valid iff SB
        if(ABF){
            #pragma unroll
            for(int u=0;u<NAB;u++){
                int t=tid+u*256;
                int off;
                if(TA){ int kk=t/(BM/8), mq=(t%(BM/8))*8; off=kk*ACols+mq; }
                else  { int row=t/(BK/8), kq=(t%(BK/8))*8; off=row*ACols+kq; }
                *(uint4*)(Ah+off)=rab[u];
            }
        }else{
            #pragma unroll
            for(int u=0;u<NAF;u++){
                int t=tid+u*256;
                float f[4]={ra[u].x,ra[u].y,ra[u].z,ra[u].w};
                __nv_bfloat16 h[4], l[4];
                #pragma unroll
                for(int q=0;q<4;q++){ h[q]=__float2bfloat16(f[q]); if(SA) l[q]=__float2bfloat16(f[q]-__bfloat162float(h[q])); }
                int off;
                if(!TA){ int row=t/(BK/4), kq=(t%(BK/4))*4; off=row*ACols+kq; }
                else   { int kk=t/(BM/4), mq=(t%(BM/4))*4; off=kk*ACols+mq; }
                __nv_bfloat162 pp;
                pp.x=h[0]; pp.y=h[1]; *(__nv_bfloat162*)(Ah+off)=pp;
                pp.x=h[2]; pp.y=h[3]; *(__nv_bfloat162*)(Ah+off+2)=pp;
                if(SA){
                    pp.x=l[0]; pp.y=l[1]; *(__nv_bfloat162*)(Al+off)=pp;
                    pp.x=l[2]; pp.y=l[3]; *(__nv_bfloat162*)(Al+off+2)=pp;
                }
            }
        }
        if(BBF){
            #pragma unroll
            for(int u=0;u<NBB;u++){
                int t=tid+u*256;
                int off;
                if(TB){ int row=t/(BK/8), kq=(t%(BK/8))*8; off=row*BCols+kq; }
                else  { int kk=t/(BN/8), nq=(t%(BN/8))*8; off=kk*BCols+nq; }
                *(uint4*)(Bh+off)=rbb[u];
            }
        }else{
            #pragma unroll
            for(int u=0;u<NBF;u++){
                int t=tid+u*256;
                float g[4]={rb[u].x,rb[u].y,rb[u].z,rb[u].w};
                __nv_bfloat16 h[4], l[4];
                #pragma unroll
                for(int q=0;q<4;q++){ h[q]=__float2bfloat16(g[q]); if(SB) l[q]=__float2bfloat16(g[q]-__bfloat162float(h[q])); }
                int off;
                if(TB){ int row=t/(BK/4), kq=(t%(BK/4))*4; off=row*BCols+kq; }
                else  { int kk=t/(BN/4), nq=(t%(BN/4))*4; off=kk*BCols+nq; }
                __nv_bfloat162 pp;
                pp.x=h[0]; pp.y=h[1]; *(__nv_bfloat162*)(Bh+off)=pp;
                pp.x=h[2]; pp.y=h[3]; *(__nv_bfloat162*)(Bh+off+2)=pp;
                if(SB){
                    pp.x=l[0]; pp.y=l[1]; *(__nv_bfloat162*)(Bl+off)=pp;
                    pp.x=l[2]; pp.y=l[3]; *(__nv_bfloat162*)(Bl+off+2)=pp;
                }
            }
        }
    };
    auto compute_stage=[&](int s){
        const unsigned aHb = sbase + (s*STG)*2;
        const unsigned aLb = aHb + ASZ*2;
        const unsigned bHb = aHb + (1+SA)*ASZ*2;
        const unsigned bLb = bHb + BSZ*2;
        #pragma unroll
        for(int kk=0;kk<BK;kk+=16){
            unsigned ah[4][4], al[4][4];
            #pragma unroll
            for(int i=0;i<4;i++){
                int mi=wm*64+i*16;
                int off = !TA ? (mi+a_m)*ACols + kk + a_k
                              : (kk+a_k)*ACols + mi + a_m;
                if(!TA){ ldsm4 (ah[i][0],ah[i][1],ah[i][2],ah[i][3], aHb+off*2);
                         if(SA) ldsm4 (al[i][0],al[i][1],al[i][2],al[i][3], aLb+off*2); }
                else   { ldsm4t(ah[i][0],ah[i][1],ah[i][2],ah[i][3], aHb+off*2);
                         if(SA) ldsm4t(al[i][0],al[i][1],al[i][2],al[i][3], aLb+off*2); }
            }
            #pragma unroll
            for(int j=0;j<4;j++){
                int nj=wn*32+j*8;
                unsigned bh[2], bl[2];
                int off = TB ? (nj+b_n)*BCols + kk + b_k
                             : (kk+b_k)*BCols + nj;
                if(TB){ ldsm2 (bh[0],bh[1], bHb+off*2);
                        if(SB) ldsm2 (bl[0],bl[1], bLb+off*2); }
                else  { ldsm2t(bh[0],bh[1], bHb+off*2);
                        if(SB) ldsm2t(bl[0],bl[1], bLb+off*2); }
                #pragma unroll
                for(int i=0;i<4;i++){
                    mma16816(acc[i][j], ah[i], bh);
                    if(SB) mma16816(acc[i][j], ah[i], bl);
                    if(SA) mma16816(acc[i][j], al[i], bh);
                }
            }
        }
    };

    // ---- 2-stage pipeline: LDG(next) -> MMA(cur) -> STS(next) -> sync ----
    const int nIter=(kend-kbeg)/BK;
    if(nIter>0){
        load_regs(kbeg);
        store_stage(0);
        __syncthreads();
        for(int it=0; it<nIter; it++){
            if(it+1<nIter) load_regs(kbeg+(it+1)*BK);
            compute_stage(it&1);
            if(it+1<nIter) store_stage((it+1)&1);
            __syncthreads();
        }
    }

    // epilogue
    #pragma unroll
    for(int i=0;i<4;i++){
        int m = m0 + wm*64 + i*16 + gid;
        #pragma unroll
        for(int j=0;j<4;j++){
            int n = n0 + wn*32 + j*8 + tig*2;
            float v0=acc[i][j][0], v1=acc[i][j][1], v2=acc[i][j][2], v3=acc[i][j][3];
            if(CBF){
                __nv_bfloat16* r0 = Cb + (size_t)m*ldc + n;
                __nv_bfloat16* r1 = Cb + (size_t)(m+8)*ldc + n;
                r0[0]=__float2bfloat16(v0); r0[1]=__float2bfloat16(v1);
                r1[0]=__float2bfloat16(v2); r1[1]=__float2bfloat16(v3);
            }else{
                float* r0 = Cf + (size_t)m*ldc + n;
                float* r1 = Cf + (size_t)(m+8)*ldc + n;
                if(EPI==EPI_STORE){ r0[0]=v0; r0[1]=v1; r1[0]=v2; r1[1]=v3; }
                else if(EPI==EPI_ADD){ r0[0]+=v0; r0[1]+=v1; r1[0]+=v2; r1[1]+=v3; }
                else if(EPI==EPI_GELU){
                    r0[0]=0.5f*v0*(1.0f+erff(v0*0.70710678118f));
                    r0[1]=0.5f*v1*(1.0f+erff(v1*0.70710678118f));
                    r1[0]=0.5f*v2*(1.0f+erff(v2*0.70710678118f));
                    r1[1]=0.5f*v3*(1.0f+erff(v3*0.70710678118f));
                }else{ // EPI_KRN
                    r0[0]=(n  <=m  )? v0*(p0/(float)(m+1))   : 0.0f;
                    r0[1]=(n+1<=m  )? v1*(p0/(float)(m+1))   : 0.0f;
                    r1[0]=(n  <=m+8)? v2*(p0/(float)(m+9))   : 0.0f;
                    r1[1]=(n+1<=m+8)? v3*(p0/(float)(m+9))   : 0.0f;
                }
            }
        }
    }
}

// fp32 -> bf16 bulk convert (n multiple of 4)
__global__ void f2bf_k(const float* __restrict__ in, __nv_bfloat16* __restrict__ out, int n){
    int i=(blockIdx.x*blockDim.x+threadIdx.x)*4;
    if(i<n){
        float4 v=*(const float4*)(in+i);
        __nv_bfloat162 a,b;
        a.x=__float2bfloat16(v.x); a.y=__float2bfloat16(v.y);
        b.x=__float2bfloat16(v.z); b.y=__float2bfloat16(v.w);
        *(__nv_bfloat162*)(out+i)=a;
        *(__nv_bfloat162*)(out+i+2)=b;
    }
}

// ---------------- layernorm over D=512 rows ----------------
__global__ void ln_rows_k(const float* __restrict__ in, const int* __restrict__ idx,
                          const float* __restrict__ w, float* __restrict__ out,
                          int rowoff, int rowstride)
{
    int r=blockIdx.x, t=threadIdx.x;
    long src = idx ? (long)idx[r] : ((long)r*rowstride + rowoff);
    const float* x = in + src*(long)Dsz;
    float4 v=*(const float4*)(x+t*4);
    float s=v.x+v.y+v.z+v.w;
    float sq=v.x*v.x+v.y*v.y+v.z*v.z+v.w*v.w;
    #pragma unroll
    for(int o=16;o;o>>=1){ s+=__shfl_xor_sync(~0u,s,o); sq+=__shfl_xor_sync(~0u,sq,o); }
    __shared__ float sa[4], sb[4];
    if((t&31)==0){ sa[t>>5]=s; sb[t>>5]=sq; }
    __syncthreads();
    s=sa[0]+sa[1]+sa[2]+sa[3]; sq=sb[0]+sb[1]+sb[2]+sb[3];
    float mu=s*(1.f/Dsz), var=sq*(1.f/Dsz)-mu*mu;
    float rs=rsqrtf(var+1e-5f);
    float4 wv=*(const float4*)(w+t*4);
    float4 o4;
    o4.x=(v.x-mu)*rs*wv.x; o4.y=(v.y-mu)*rs*wv.y;
    o4.z=(v.z-mu)*rs*wv.z; o4.w=(v.w-mu)*rs*wv.w;
    *(float4*)(out+(size_t)r*Dsz+t*4)=o4;
}

// Aq[h,s,d]=p[s+1,d]*Wq[h,d];  Bk[h,s,d]=p[s,d]*Wk[h,d]
__global__ void qk_prep_k(const float* __restrict__ p, const float* __restrict__ Wq,
                          const float* __restrict__ Wk, float* __restrict__ Aq, float* __restrict__ Bk)
{
    int i=blockIdx.x*blockDim.x+threadIdx.x;
    if(i>=Hsz*Ssz*Dsz) return;
    int d=i%Dsz, s=(i/Dsz)%Ssz, h=i/(Dsz*Ssz);
    Aq[i]=p[(s+1)*Dsz+d]*Wq[h*Dsz+d];
    Bk[i]=p[s*Dsz+d]*Wk[h*Dsz+d];
}

__global__ void colmean_part_k(const float* __restrict__ wte, float* __restrict__ cmP){
    int d=threadIdx.x, c=blockIdx.x;
    const int rows=Vsz/CMCH;
    float s=0;
    for(int v=c*rows; v<(c+1)*rows; v++) s+=wte[(size_t)v*Dsz+d];
    cmP[c*Dsz+d]=s;
}
__global__ void colmean_red_k(const float* __restrict__ cmP, float* __restrict__ cm){
    int d=threadIdx.x; float s=0;
    for(int c=0;c<CMCH;c++) s+=cmP[c*Dsz+d];
    cm[d]=s*(1.0f/Vsz);
}

__global__ void zero_k(float* __restrict__ p, int n){
    int i=blockIdx.x*blockDim.x+threadIdx.x;
    if(i<n) p[i]=0.f;
}

// iteration 0: Vt = e - colmean(wte)
__global__ void vt0_k(const float* __restrict__ e, const float* __restrict__ cm, float* __restrict__ Vt){
    int i=blockIdx.x*blockDim.x+threadIdx.x;
    if(i<Bsz*Ssz*Dsz) Vt[i]=e[i]-cm[i&(Dsz-1)];
}

// in-place row softmax of bf16 R (rows of length S=1024), 128 threads x 8 elems
__global__ void softmax_rows_bf_k(__nv_bfloat16* __restrict__ R){
    __nv_bfloat16* p=R+(size_t)blockIdx.x*Ssz;
    int t=threadIdx.x;   // 128
    uint4 u=*(uint4*)(p+t*8);
    __nv_bfloat162* hp=(__nv_bfloat162*)&u;
    float v[8];
    #pragma unroll
    for(int i=0;i<4;i++){ v[2*i]=__bfloat162float(hp[i].x); v[2*i+1]=__bfloat162float(hp[i].y); }
    float mx=v[0];
    #pragma unroll
    for(int i=1;i<8;i++) mx=fmaxf(mx,v[i]);
    #pragma unroll
    for(int o=16;o;o>>=1) mx=fmaxf(mx,__shfl_xor_sync(~0u,mx,o));
    __shared__ float sm[4], ss[4];
    if((t&31)==0) sm[t>>5]=mx;
    __syncthreads();
    float m2=fmaxf(fmaxf(sm[0],sm[1]),fmaxf(sm[2],sm[3]));
    float s=0;
    #pragma unroll
    for(int i=0;i<8;i++){ v[i]=__expf(v[i]-m2); s+=v[i]; }
    #pragma unroll
    for(int o=16;o;o>>=1) s+=__shfl_xor_sync(~0u,s,o);
    if((t&31)==0) ss[t>>5]=s;
    __syncthreads();
    float inv=1.f/(ss[0]+ss[1]+ss[2]+ss[3]);
    #pragma unroll
    for(int i=0;i<4;i++){
        hp[i].x=__float2bfloat16(v[2*i]*inv);
        hp[i].y=__float2bfloat16(v[2*i+1]*inv);
    }
    *(uint4*)(p+t*8)=u;
}

// rsum partials: rsP[c][b][s] = sum over v-chunk c of R[b,v,s]  (bf16 R)
__global__ void colsum_k(const __nv_bfloat16* __restrict__ R, float* __restrict__ rsP){
    int s=blockIdx.x*blockDim.x+threadIdx.x;
    int b=blockIdx.y, c=blockIdx.z;
    const int rows=Vsz/CSCH;
    const __nv_bfloat16* p=R+(size_t)b*Vsz*Ssz+(size_t)c*rows*Ssz+s;
    float acc=0;
    for(int v=0;v<rows;v++) acc+=__bfloat162float(p[(size_t)v*Ssz]);
    rsP[(size_t)c*Bsz*Ssz+b*Ssz+s]=acc;
}

// iteration 1: Vt = e - (sum_ks exP)/(sum_c rsP)
__global__ void vt1_k(const float* __restrict__ e, const float* __restrict__ exP,
                      const float* __restrict__ rsP, float* __restrict__ Vt){
    int i=blockIdx.x*blockDim.x+threadIdx.x;
    if(i>=Bsz*Ssz*Dsz) return;
    int d=i&(Dsz-1), s=(i>>9)&(Ssz-1), b=i>>19;
    float ex=0;
    #pragma unroll
    for(int c=0;c<KS;c++) ex+=exP[((size_t)(b*KS+c))*Ssz*Dsz+(size_t)s*Dsz+d];
    float rs=0;
    #pragma unroll
    for(int c=0;c<CSCH;c++) rs+=rsP[(size_t)c*Bsz*Ssz+b*Ssz+s];
    Vt[i]=e[i]-ex/rs;
}

// final: out[b,v] = oln[b,:] . wte[v,:]   (one warp per v, both batches)
__global__ void final_logits_k(const float* __restrict__ oln, const float* __restrict__ wte,
                               float* __restrict__ out){
    int gw=(blockIdx.x*blockDim.x+threadIdx.x)>>5;
    int lane=threadIdx.x&31;
    if(gw>=Vsz) return;
    const float* wr=wte+(size_t)gw*Dsz;
    #pragma unroll
    for(int b=0;b<Bsz;b++){
        float s=0;
        for(int k=lane*4;k<Dsz;k+=128){
            float4 w4=*(const float4*)(wr+k);
            float4 x4=*(const float4*)(oln+b*Dsz+k);
            s+=w4.x*x4.x+w4.y*x4.y+w4.z*x4.z+w4.w*x4.w;
        }
        #pragma unroll
        for(int o=16;o;o>>=1) s+=__shfl_xor_sync(~0u,s,o);
        if(lane==0) out[b*Vsz+gw]=s;
    }
}

// ---------------- orchestration ----------------
extern "C" void kernel_launch(void* const* d_in, const int* in_sizes, int n_in,
                              void* d_out, int out_size)
{
    const int*   x     =(const int*)  d_in[0];
    const float* wte   =(const float*)d_in[1];
    const float* wpe   =(const float*)d_in[2];
    const float* ln_e  =(const float*)d_in[3];
    const float* ln_p  =(const float*)d_in[4];
    const float* ln_f  =(const float*)d_in[5];
    const float* ln_mlp=(const float*)d_in[6];
    const float* Wq    =(const float*)d_in[7];
    const float* Wk    =(const float*)d_in[8];
    const float* Wo    =(const float*)d_in[9];
    const float* w1    =(const float*)d_in[10];
    const float* w2    =(const float*)d_in[11];
    float* out=(float*)d_out;

    float *e,*p,*Aq,*Bk,*krn,*fk,*Vt,*attn,*hln,*act,*exP,*rsP,*cmP,*cm,*oln;
    __nv_bfloat16 *R,*wteh,*fkh;
    cudaGetSymbolAddress((void**)&e,   d_e);
    cudaGetSymbolAddress((void**)&p,   d_p);
    cudaGetSymbolAddress((void**)&Aq,  d_Aq);
    cudaGetSymbolAddress((void**)&Bk,  d_Bk);
    cudaGetSymbolAddress((void**)&krn, d_krn);
    cudaGetSymbolAddress((void**)&fk,  d_fk);
    cudaGetSymbolAddress((void**)&Vt,  d_Vt);
    cudaGetSymbolAddress((void**)&attn,d_attn);
    cudaGetSymbolAddress((void**)&hln, d_hln);
    cudaGetSymbolAddress((void**)&act, d_act);
    cudaGetSymbolAddress((void**)&R,   d_R);
    cudaGetSymbolAddress((void**)&wteh,d_wteh);
    cudaGetSymbolAddress((void**)&fkh, d_fkh);
    cudaGetSymbolAddress((void**)&exP, d_exP);
    cudaGetSymbolAddress((void**)&rsP, d_rsP);
    cudaGetSymbolAddress((void**)&cmP, d_cmP);
    cudaGetSymbolAddress((void**)&cm,  d_cm);
    cudaGetSymbolAddress((void**)&oln, d_oln);

    const float invsqD = 1.0f/sqrtf((float)Dsz);

    // raise dynamic smem limits (idempotent)
    cudaFuncSetAttribute(mma_k<false,true ,1,1,false,false,false,EPI_KRN  ,32>, cudaFuncAttributeMaxDynamicSharedMemorySize, smem_bytes<false,true ,1,1,32>());
    cudaFuncSetAttribute(mma_k<false,true ,0,0,true ,true ,true ,EPI_STORE,64>, cudaFuncAttributeMaxDynamicSharedMemorySize, smem_bytes<false,true ,0,0,64>());
    cudaFuncSetAttribute(mma_k<true ,false,0,0,true ,true ,false,EPI_STORE,64>, cudaFuncAttributeMaxDynamicSharedMemorySize, smem_bytes<true ,false,0,0,64>());
    cudaFuncSetAttribute(mma_k<false,false,1,1,false,false,false,EPI_STORE,32>, cudaFuncAttributeMaxDynamicSharedMemorySize, smem_bytes<false,false,1,1,32>());
    cudaFuncSetAttribute(mma_k<false,true ,1,1,false,false,false,EPI_ADD  ,32>, cudaFuncAttributeMaxDynamicSharedMemorySize, smem_bytes<false,true ,1,1,32>());
    cudaFuncSetAttribute(mma_k<false,true ,1,1,false,false,false,EPI_GELU ,32>, cudaFuncAttributeMaxDynamicSharedMemorySize, smem_bytes<false,true ,1,1,32>());

    // embeddings + positional LN + one-time wte bf16 conversion
    ln_rows_k<<<Bsz*Ssz,128>>>(wte, x,       ln_e, e, 0, 1);
    ln_rows_k<<<Ssz+1,  128>>>(wpe, nullptr, ln_p, p, 0, 1);
    qk_prep_k<<<(Hsz*Ssz*Dsz+255)/256,256>>>(p, Wq, Wk, Aq, Bk);
    colmean_part_k<<<CMCH,Dsz>>>(wte, cmP);
    colmean_red_k<<<1,Dsz>>>(cmP, cm);
    f2bf_k<<<(Vsz*Dsz/4+255)/256,256>>>(wte, wteh, Vsz*Dsz);

    // krn[h,s,t] = (Aq[h,s,:].Bk[h,t,:]) / sqrt(D) / (s+1), causal-masked  [split-2]
    mma_k<false,true,1,1,false,false,false,EPI_KRN,32><<<dim3(Ssz/128,Ssz/128,Hsz),256,smem_bytes<false,true,1,1,32>()>>>(
        Ssz,Ssz,Dsz, Aq,Bk,krn, Dsz,Dsz,Ssz,
        Hsz, 0,(ll)Ssz*Dsz, 0,(ll)Ssz*Dsz, 0,(ll)Ssz*Ssz, 1, 0, invsqD);

    zero_k<<<(Bsz*Ssz*Dsz+255)/256,256>>>(fk, Bsz*Ssz*Dsz);

    for(int it=0; it<2; it++){
        if(it==0){
            vt0_k<<<(Bsz*Ssz*Dsz+255)/256,256>>>(e, cm, Vt);
        }else{
            // fk -> bf16
            f2bf_k<<<(Bsz*Ssz*Dsz/4+255)/256,256>>>(fk, fkh, Bsz*Ssz*Dsz);
            // logits R[b,v,s] = wte[v,:] . fk[b,s,:]   [pure bf16, BK=64, bf16 out]
            mma_k<false,true,0,0,true,true,true,EPI_STORE,64><<<dim3(Ssz/128,Vsz/128,Bsz),256,smem_bytes<false,true,0,0,64>()>>>(
                Vsz,Ssz,Dsz, wteh,fkh,R, Dsz,Dsz,Ssz,
                1, 0,0, (ll)Ssz*Dsz,0, (ll)Vsz*Ssz,0, 1, 0, 0.f);
            softmax_rows_bf_k<<<Bsz*Vsz,128>>>(R);
            colsum_k<<<dim3(Ssz/256,Bsz,CSCH),256>>>(R, rsP);
            // ex_wte[b,s,d] = sum_v R[b,v,s]*wte[v,d]   [pure bf16, BK=64, split-K=10]
            mma_k<true,false,0,0,true,true,false,EPI_STORE,64><<<dim3(Dsz/128,Ssz/128,Bsz*KS),256,smem_bytes<true,false,0,0,64>()>>>(
                Ssz,Dsz,Vsz, R,wteh,exP, Ssz,Dsz,Dsz,
                KS, (ll)Vsz*Ssz,0, 0,0, (ll)KS*Ssz*Dsz,(ll)Ssz*Dsz, KS, 0, 0.f);
            vt1_k<<<(Bsz*Ssz*Dsz+255)/256,256>>>(e, exP, rsP, Vt);
        }
        // attn[b,s,h*D+d] = sum_t krn[h,s,t]*Vt[b,t,d]  [split-2, causal triK]
        mma_k<false,false,1,1,false,false,false,EPI_STORE,32><<<dim3(Dsz/128,Ssz/128,Bsz*Hsz),256,smem_bytes<false,false,1,1,32>()>>>(
            Ssz,Dsz,Ssz, krn,Vt,attn, Ssz,Dsz,Hsz*Dsz,
            Hsz, 0,(ll)Ssz*Ssz, (ll)Ssz*Dsz,0, (ll)Ssz*Hsz*Dsz,(ll)Dsz, 1, 1, 0.f);
        // fk += attn @ Wo[it]^T  [split-2]
        mma_k<false,true,1,1,false,false,false,EPI_ADD,32><<<dim3(Dsz/128,(Bsz*Ssz)/128,1),256,smem_bytes<false,true,1,1,32>()>>>(
            Bsz*Ssz,Dsz,Hsz*Dsz, attn, Wo+(size_t)it*Dsz*Hsz*Dsz, fk, Hsz*Dsz,Hsz*Dsz,Dsz,
            1, 0,0,0,0,0,0, 1, 0, 0.f);
        // MLP  [split-2]
        ln_rows_k<<<Bsz*Ssz,128>>>(fk, nullptr, ln_mlp, hln, 0, 1);
        mma_k<false,true,1,1,false,false,false,EPI_GELU,32><<<dim3(DFFsz/128,(Bsz*Ssz)/128,1),256,smem_bytes<false,true,1,1,32>()>>>(
            Bsz*Ssz,DFFsz,Dsz, hln,w1,act, Dsz,Dsz,DFFsz,
            1, 0,0,0,0,0,0, 1, 0, 0.f);
        mma_k<false,true,1,1,false,false,false,EPI_ADD,32><<<dim3(Dsz/128,(Bsz*Ssz)/128,1),256,smem_bytes<false,true,1,1,32>()>>>(
            Bsz*Ssz,Dsz,DFFsz, act,w2,fk, DFFsz,DFFsz,Dsz,
            1, 0,0,0,0,0,0, 1, 0, 0.f);
    }

    // final LN of last token per batch, then logits vs wte
    ln_rows_k<<<Bsz,128>>>(fk, nullptr, ln_f, oln, Ssz-1, Ssz);
    final_logits_k<<<(Vsz*32+255)/256,256>>>(oln, wte, out);
}

// round 15
// speedup vs baseline: 1.3666x; 1.3666x over previous
#include <cuda_runtime.h>
#include <cuda_bf16.h>
#include <math.h>

// Problem constants
#define Bsz   2
#define Ssz   1024
#define Dsz   512
#define Hsz   8
#define Vsz   32000
#define DFFsz 2048
#define KS    8      // split-K factor for ex_wte GEMM (32000/8=4000, 4000/32=125)
#define CSCH  16     // chunks for column-sum of R
#define CMCH  128    // chunks for column-mean of wte

typedef long long ll;

// ---------------- device scratch (no allocations allowed) ----------------
__device__ float d_e  [Bsz*Ssz*Dsz];
__device__ float d_p  [(Ssz+1)*Dsz];
__device__ float d_Aq [Hsz*Ssz*Dsz];
__device__ float d_Bk [Hsz*Ssz*Dsz];
__device__ float d_krn[(size_t)Hsz*Ssz*Ssz];
__device__ float d_fk [Bsz*Ssz*Dsz];
__device__ float d_Vt [Bsz*Ssz*Dsz];
__device__ float d_attn[(size_t)Bsz*Ssz*Hsz*Dsz];
__device__ float d_hln[Bsz*Ssz*Dsz];
__device__ float d_act[Bsz*Ssz*DFFsz];
__device__ __nv_bfloat16 d_R[(size_t)Bsz*Vsz*Ssz];   // 131 MB (bf16)
__device__ __nv_bfloat16 d_wteh[(size_t)Vsz*Dsz];    // 33 MB  (bf16 wte)
__device__ __nv_bfloat16 d_fkh[Bsz*Ssz*Dsz];         // 4 MB   (bf16 fk)
__device__ float d_exP[(size_t)Bsz*KS*Ssz*Dsz];
__device__ float d_rsP[CSCH*Bsz*Ssz];
__device__ float d_cmP[CMCH*Dsz];
__device__ float d_cm [Dsz];
__device__ float d_oln[Bsz*Dsz];

enum { EPI_STORE=0, EPI_ADD=1, EPI_GELU=2, EPI_KRN=3 };

// ---------------- ldmatrix / mma wrappers ----------------
__device__ __forceinline__ void ldsm4(unsigned &r0,unsigned &r1,unsigned &r2,unsigned &r3,unsigned a){
    asm volatile("ldmatrix.sync.aligned.m8n8.x4.shared.b16 {%0,%1,%2,%3},[%4];"
        :"=r"(r0),"=r"(r1),"=r"(r2),"=r"(r3):"r"(a));
}
__device__ __forceinline__ void ldsm4t(unsigned &r0,unsigned &r1,unsigned &r2,unsigned &r3,unsigned a){
    asm volatile("ldmatrix.sync.aligned.m8n8.x4.trans.shared.b16 {%0,%1,%2,%3},[%4];"
        :"=r"(r0),"=r"(r1),"=r"(r2),"=r"(r3):"r"(a));
}
__device__ __forceinline__ void ldsm2(unsigned &r0,unsigned &r1,unsigned a){
    asm volatile("ldmatrix.sync.aligned.m8n8.x2.shared.b16 {%0,%1},[%2];"
        :"=r"(r0),"=r"(r1):"r"(a));
}
__device__ __forceinline__ void ldsm2t(unsigned &r0,unsigned &r1,unsigned a){
    asm volatile("ldmatrix.sync.aligned.m8n8.x2.trans.shared.b16 {%0,%1},[%2];"
        :"=r"(r0),"=r"(r1):"r"(a));
}
__device__ __forceinline__ void mma16816(float* c,const unsigned* a,const unsigned* b){
    asm volatile("mma.sync.aligned.m16n8k16.row.col.f32.bf16.bf16.f32 "
        "{%0,%1,%2,%3},{%4,%5,%6,%7},{%8,%9},{%0,%1,%2,%3};"
        : "+f"(c[0]),"+f"(c[1]),"+f"(c[2]),"+f"(c[3])
        : "r"(a[0]),"r"(a[1]),"r"(a[2]),"r"(a[3]),"r"(b[0]),"r"(b[1]));
}

// dynamic smem bytes: 2 stages x ((1+SA)*A + (1+SB)*B) bf16 tiles
template<bool TA,bool TB,int SA,int SB,int BKT> constexpr int smem_bytes(){
    constexpr int ASZ=(TA?BKT:128)*(TA?136:BKT+8);
    constexpr int BSZ=(TB?128:BKT)*(TB?BKT+8:136);
    return 2*((1+SA)*ASZ+(1+SB)*BSZ)*2;
}

// ---------------- bf16 tensor-core GEMM, tiered precision, double-buffered ----
// C(MxN)=A(MxK)*B(KxN). TA: A stored KxM. TB: B stored NxK.
// SA/SB: operand split x=hi+lo (bf16 each). Products: Ah*Bh [+ Ah*Bl if SB]
// [+ Al*Bh if SA], fp32 accum. ABF/BBF: operand already bf16 in gmem (raw copy
// staging, forces that split off). CBF: C written bf16.
// Batched via blockIdx.z (z1=z/Z2, z2=z%Z2). Ksplit>1: z2 picks K-slice.
// triK: kend=min(kend,m0+BM) (causal contraction). 256 thr = 8 warps (2Mx4N).
template<bool TA,bool TB,int SA,int SB,bool ABF,bool BBF,bool CBF,int EPI,int BKT>
__global__ void __launch_bounds__(256,1)
mma_k(int M,int N,int K,
      const void* __restrict__ Av,const void* __restrict__ Bv,void* __restrict__ Cv,
      int lda,int ldb,int ldc,
      int Z2, ll sA1, ll sA2, ll sB1, ll sB2, ll sC1, ll sC2,
      int Ksplit, int triK, float p0)
{
    constexpr int BM=128, BN=128, BK=BKT;
    constexpr int ACols = TA ? BM+8 : BK+8;
    constexpr int BCols = TB ? BK+8 : BN+8;
    constexpr int ARows = TA ? BK : BM;
    constexpr int BRows = TB ? BN : BK;
    constexpr int ASZ = ARows*ACols;
    constexpr int BSZ = BRows*BCols;
    constexpr int STG = (1+SA)*ASZ + (1+SB)*BSZ;   // elems per stage
    constexpr int NAF = BM*BK/1024;   // float4 passes for A (256 thr)
    constexpr int NAB = BM*BK/2048;   // uint4  passes for A
    constexpr int NBF = BN*BK/1024;
    constexpr int NBB = BN*BK/2048;

    extern __shared__ __align__(16) __nv_bfloat16 S[];

    const int z=blockIdx.z, z1=z/Z2, z2=z%Z2;
    const float*         Af=(const float*)Av + z1*sA1 + z2*sA2;
    const __nv_bfloat16* Ab=(const __nv_bfloat16*)Av + z1*sA1 + z2*sA2;
    const float*         Bf=(const float*)Bv + z1*sB1 + z2*sB2;
    const __nv_bfloat16* Bb=(const __nv_bfloat16*)Bv + z1*sB1 + z2*sB2;
    float*         Cf=(float*)Cv + z1*sC1 + z2*sC2;
    __nv_bfloat16* Cb=(__nv_bfloat16*)Cv + z1*sC1 + z2*sC2;
    const int m0=blockIdx.y*BM, n0=blockIdx.x*BN;

    int kbeg=0, kend=K;
    if (Ksplit>1){ int kc=K/Ksplit; kbeg=z2*kc; kend=kbeg+kc; }
    if (triK && kend > m0+BM) kend = m0+BM;
    if (EPI==EPI_KRN && n0 >= m0+BM) kend = kbeg;   // fully masked tile: skip mainloop

    const int tid=threadIdx.x;
    const int lane=tid&31, wid=tid>>5;
    const int wm=wid&1, wn=wid>>1;
    const int gid=lane>>2, tig=lane&3;

    // ldmatrix per-lane offset components
    int a_m, a_k;
    if(!TA){ a_m=(lane&7)+((lane&8)?8:0); a_k=(lane&16)?8:0; }
    else   { a_k=(lane&7)+((lane&16)?8:0); a_m=(lane&8)?8:0; }
    const int l16=lane&15;
    int b_n, b_k;
    if(TB){ b_n=l16&7;                 b_k=(l16&8)?8:0; }
    else  { b_k=(l16&7)+((l16&8)?8:0); b_n=0; }

    const unsigned sbase=(unsigned)__cvta_generic_to_shared(S);

    float acc[4][4][4];
    #pragma unroll
    for(int i=0;i<4;i++)
        #pragma unroll
        for(int j=0;j<4;j++)
            #pragma unroll
            for(int r=0;r<4;r++) acc[i][j][r]=0.f;

    float4 ra[ABF?1:NAF]; uint4 rab[ABF?NAB:1];
    float4 rb[BBF?1:NBF]; uint4 rbb[BBF?NBB:1];

    // ---- staged-load helpers ----
    auto load_regs=[&](int kk0){
        if(ABF){
            #pragma unroll
            for(int u=0;u<NAB;u++){
                int t=tid+u*256;
                if(TA){ int kk=t/(BM/8), mq=(t%(BM/8))*8; rab[u]=*(const uint4*)(Ab+(size_t)(kk0+kk)*lda+m0+mq); }
                else  { int row=t/(BK/8), kq=(t%(BK/8))*8; rab[u]=*(const uint4*)(Ab+(size_t)(m0+row)*lda+kk0+kq); }
            }
        }else{
            #pragma unroll
            for(int u=0;u<NAF;u++){
                int t=tid+u*256;
                if(!TA){ int row=t/(BK/4), kq=(t%(BK/4))*4; ra[u]=*(const float4*)(Af+(size_t)(m0+row)*lda+kk0+kq); }
                else   { int kk=t/(BM/4), mq=(t%(BM/4))*4; ra[u]=*(const float4*)(Af+(size_t)(kk0+kk)*lda+m0+mq); }
            }
        }
        if(BBF){
            #pragma unroll
            for(int u=0;u<NBB;u++){
                int t=tid+u*256;
                if(TB){ int row=t/(BK/8), kq=(t%(BK/8))*8; rbb[u]=*(const uint4*)(Bb+(size_t)(n0+row)*ldb+kk0+kq); }
                else  { int kk=t/(BN/8), nq=(t%(BN/8))*8; rbb[u]=*(const uint4*)(Bb+(size_t)(kk0+kk)*ldb+n0+nq); }
            }
        }else{
            #pragma unroll
            for(int u=0;u<NBF;u++){
                int t=tid+u*256;
                if(TB) { int row=t/(BK/4), kq=(t%(BK/4))*4; rb[u]=*(const float4*)(Bf+(size_t)(n0+row)*ldb+kk0+kq); }
                else   { int kk=t/(BN/4), nq=(t%(BN/4))*4; rb[u]=*(const float4*)(Bf+(size_t)(kk0+kk)*ldb+n0+nq); }
            }
        }
    };
    auto store_stage=[&](int s){
        __nv_bfloat16* Ah = S + s*STG;
        __nv_bfloat16* Al = Ah + ASZ;                  // valid iff SA
        __nv_bfloat16* Bh = Ah + (1+SA)*ASZ;
        __nv_bfloat16* Bl = Bh + BSZ;                  // valid iff SB
        if(ABF){
            #pragma unroll
            for(int u=0;u<NAB;u++){
                int t=tid+u*256;
                int off;
                if(TA){ int kk=t/(BM/8), mq=(t%(BM/8))*8; off=kk*ACols+mq; }
                else  { int row=t/(BK/8), kq=(t%(BK/8))*8; off=row*ACols+kq; }
                *(uint4*)(Ah+off)=rab[u];
            }
        }else{
            #pragma unroll
            for(int u=0;u<NAF;u++){
                int t=tid+u*256;
                float f[4]={ra[u].x,ra[u].y,ra[u].z,ra[u].w};
                __nv_bfloat16 h[4], l[4];
                #pragma unroll
                for(int q=0;q<4;q++){ h[q]=__float2bfloat16(f[q]); if(SA) l[q]=__float2bfloat16(f[q]-__bfloat162float(h[q])); }
                int off;
                if(!TA){ int row=t/(BK/4), kq=(t%(BK/4))*4; off=row*ACols+kq; }
                else   { int kk=t/(BM/4), mq=(t%(BM/4))*4; off=kk*ACols+mq; }
                __nv_bfloat162 pp;
                pp.x=h[0]; pp.y=h[1]; *(__nv_bfloat162*)(Ah+off)=pp;
                pp.x=h[2]; pp.y=h[3]; *(__nv_bfloat162*)(Ah+off+2)=pp;
                if(SA){
                    pp.x=l[0]; pp.y=l[1]; *(__nv_bfloat162*)(Al+off)=pp;
                    pp.x=l[2]; pp.y=l[3]; *(__nv_bfloat162*)(Al+off+2)=pp;
                }
            }
        }
        if(BBF){
            #pragma unroll
            for(int u=0;u<NBB;u++){
                int t=tid+u*256;
                int off;
                if(TB){ int row=t/(BK/8), kq=(t%(BK/8))*8; off=row*BCols+kq; }
                else  { int kk=t/(BN/8), nq=(t%(BN/8))*8; off=kk*BCols+nq; }
                *(uint4*)(Bh+off)=rbb[u];
            }
        }else{
            #pragma unroll
            for(int u=0;u<NBF;u++){
                int t=tid+u*256;
                float g[4]={rb[u].x,rb[u].y,rb[u].z,rb[u].w};
                __nv_bfloat16 h[4], l[4];
                #pragma unroll
                for(int q=0;q<4;q++){ h[q]=__float2bfloat16(g[q]); if(SB) l[q]=__float2bfloat16(g[q]-__bfloat162float(h[q])); }
                int off;
                if(TB){ int row=t/(BK/4), kq=(t%(BK/4))*4; off=row*BCols+kq; }
                else  { int kk=t/(BN/4), nq=(t%(BN/4))*4; off=kk*BCols+nq; }
                __nv_bfloat162 pp;
                pp.x=h[0]; pp.y=h[1]; *(__nv_bfloat162*)(Bh+off)=pp;
                pp.x=h[2]; pp.y=h[3]; *(__nv_bfloat162*)(Bh+off+2)=pp;
                if(SB){
                    pp.x=l[0]; pp.y=l[1]; *(__nv_bfloat162*)(Bl+off)=pp;
                    pp.x=l[2]; pp.y=l[3]; *(__nv_bfloat162*)(Bl+off+2)=pp;
                }
            }
        }
    };
    auto compute_stage=[&](int s){
        const unsigned aHb = sbase + (s*STG)*2;
        const unsigned aLb = aHb + ASZ*2;
        const unsigned bHb = aHb + (1+SA)*ASZ*2;
        const unsigned bLb = bHb + BSZ*2;
        #pragma unroll
        for(int kk=0;kk<BK;kk+=16){
            unsigned ah[4][4], al[4][4];
            #pragma unroll
            for(int i=0;i<4;i++){
                int mi=wm*64+i*16;
                int off = !TA ? (mi+a_m)*ACols + kk + a_k
                              : (kk+a_k)*ACols + mi + a_m;
                if(!TA){ ldsm4 (ah[i][0],ah[i][1],ah[i][2],ah[i][3], aHb+off*2);
                         if(SA) ldsm4 (al[i][0],al[i][1],al[i][2],al[i][3], aLb+off*2); }
                else   { ldsm4t(ah[i][0],ah[i][1],ah[i][2],ah[i][3], aHb+off*2);
                         if(SA) ldsm4t(al[i][0],al[i][1],al[i][2],al[i][3], aLb+off*2); }
            }
            #pragma unroll
            for(int j=0;j<4;j++){
                int nj=wn*32+j*8;
                unsigned bh[2], bl[2];
                int off = TB ? (nj+b_n)*BCols + kk + b_k
                             : (kk+b_k)*BCols + nj;
                if(TB){ ldsm2 (bh[0],bh[1], bHb+off*2);
                        if(SB) ldsm2 (bl[0],bl[1], bLb+off*2); }
                else  { ldsm2t(bh[0],bh[1], bHb+off*2);
                        if(SB) ldsm2t(bl[0],bl[1], bLb+off*2); }
                #pragma unroll
                for(int i=0;i<4;i++){
                    mma16816(acc[i][j], ah[i], bh);
                    if(SB) mma16816(acc[i][j], ah[i], bl);
                    if(SA) mma16816(acc[i][j], al[i], bh);
                }
            }
        }
    };

    // ---- 2-stage pipeline: LDG(next) -> MMA(cur) -> STS(next) -> sync ----
    const int nIter=(kend-kbeg)/BK;
    if(nIter>0){
        load_regs(kbeg);
        store_stage(0);
        __syncthreads();
        for(int it=0; it<nIter; it++){
            if(it+1<nIter) load_regs(kbeg+(it+1)*BK);
            compute_stage(it&1);
            if(it+1<nIter) store_stage((it+1)&1);
            __syncthreads();
        }
    }

    // epilogue
    #pragma unroll
    for(int i=0;i<4;i++){
        int m = m0 + wm*64 + i*16 + gid;
        #pragma unroll
        for(int j=0;j<4;j++){
            int n = n0 + wn*32 + j*8 + tig*2;
            float v0=acc[i][j][0], v1=acc[i][j][1], v2=acc[i][j][2], v3=acc[i][j][3];
            if(CBF){
                __nv_bfloat16* r0 = Cb + (size_t)m*ldc + n;
                __nv_bfloat16* r1 = Cb + (size_t)(m+8)*ldc + n;
                r0[0]=__float2bfloat16(v0); r0[1]=__float2bfloat16(v1);
                r1[0]=__float2bfloat16(v2); r1[1]=__float2bfloat16(v3);
            }else{
                float* r0 = Cf + (size_t)m*ldc + n;
                float* r1 = Cf + (size_t)(m+8)*ldc + n;
                if(EPI==EPI_STORE){ r0[0]=v0; r0[1]=v1; r1[0]=v2; r1[1]=v3; }
                else if(EPI==EPI_ADD){ r0[0]+=v0; r0[1]+=v1; r1[0]+=v2; r1[1]+=v3; }
                else if(EPI==EPI_GELU){
                    r0[0]=0.5f*v0*(1.0f+erff(v0*0.70710678118f));
                    r0[1]=0.5f*v1*(1.0f+erff(v1*0.70710678118f));
                    r1[0]=0.5f*v2*(1.0f+erff(v2*0.70710678118f));
                    r1[1]=0.5f*v3*(1.0f+erff(v3*0.70710678118f));
                }else{ // EPI_KRN
                    r0[0]=(n  <=m  )? v0*(p0/(float)(m+1))   : 0.0f;
                    r0[1]=(n+1<=m  )? v1*(p0/(float)(m+1))   : 0.0f;
                    r1[0]=(n  <=m+8)? v2*(p0/(float)(m+9))   : 0.0f;
                    r1[1]=(n+1<=m+8)? v3*(p0/(float)(m+9))   : 0.0f;
                }
            }
        }
    }
}

// fp32 -> bf16 bulk convert (n multiple of 4)
__global__ void f2bf_k(const float* __restrict__ in, __nv_bfloat16* __restrict__ out, int n){
    int i=(blockIdx.x*blockDim.x+threadIdx.x)*4;
    if(i<n){
        float4 v=*(const float4*)(in+i);
        __nv_bfloat162 a,b;
        a.x=__float2bfloat16(v.x); a.y=__float2bfloat16(v.y);
        b.x=__float2bfloat16(v.z); b.y=__float2bfloat16(v.w);
        *(__nv_bfloat162*)(out+i)=a;
        *(__nv_bfloat162*)(out+i+2)=b;
    }
}

// ---------------- layernorm over D=512 rows ----------------
__global__ void ln_rows_k(const float* __restrict__ in, const int* __restrict__ idx,
                          const float* __restrict__ w, float* __restrict__ out,
                          int rowoff, int rowstride)
{
    int r=blockIdx.x, t=threadIdx.x;
    long src = idx ? (long)idx[r] : ((long)r*rowstride + rowoff);
    const float* x = in + src*(long)Dsz;
    float4 v=*(const float4*)(x+t*4);
    float s=v.x+v.y+v.z+v.w;
    float sq=v.x*v.x+v.y*v.y+v.z*v.z+v.w*v.w;
    #pragma unroll
    for(int o=16;o;o>>=1){ s+=__shfl_xor_sync(~0u,s,o); sq+=__shfl_xor_sync(~0u,sq,o); }
    __shared__ float sa[4], sb[4];
    if((t&31)==0){ sa[t>>5]=s; sb[t>>5]=sq; }
    __syncthreads();
    s=sa[0]+sa[1]+sa[2]+sa[3]; sq=sb[0]+sb[1]+sb[2]+sb[3];
    float mu=s*(1.f/Dsz), var=sq*(1.f/Dsz)-mu*mu;
    float rs=rsqrtf(var+1e-5f);
    float4 wv=*(const float4*)(w+t*4);
    float4 o4;
    o4.x=(v.x-mu)*rs*wv.x; o4.y=(v.y-mu)*rs*wv.y;
    o4.z=(v.z-mu)*rs*wv.z; o4.w=(v.w-mu)*rs*wv.w;
    *(float4*)(out+(size_t)r*Dsz+t*4)=o4;
}

// Aq[h,s,d]=p[s+1,d]*Wq[h,d];  Bk[h,s,d]=p[s,d]*Wk[h,d]
__global__ void qk_prep_k(const float* __restrict__ p, const float* __restrict__ Wq,
                          const float* __restrict__ Wk, float* __restrict__ Aq, float* __restrict__ Bk)
{
    int i=blockIdx.x*blockDim.x+threadIdx.x;
    if(i>=Hsz*Ssz*Dsz) return;
    int d=i%Dsz, s=(i/Dsz)%Ssz, h=i/(Dsz*Ssz);
    Aq[i]=p[(s+1)*Dsz+d]*Wq[h*Dsz+d];
    Bk[i]=p[s*Dsz+d]*Wk[h*Dsz+d];
}

__global__ void colmean_part_k(const float* __restrict__ wte, float* __restrict__ cmP){
    int d=threadIdx.x, c=blockIdx.x;
    const int rows=Vsz/CMCH;
    float s=0;
    for(int v=c*rows; v<(c+1)*rows; v++) s+=wte[(size_t)v*Dsz+d];
    cmP[c*Dsz+d]=s;
}
__global__ void colmean_red_k(const float* __restrict__ cmP, float* __restrict__ cm){
    int d=threadIdx.x; float s=0;
    for(int c=0;c<CMCH;c++) s+=cmP[c*Dsz+d];
    cm[d]=s*(1.0f/Vsz);
}

__global__ void zero_k(float* __restrict__ p, int n){
    int i=blockIdx.x*blockDim.x+threadIdx.x;
    if(i<n) p[i]=0.f;
}

// iteration 0: Vt = e - colmean(wte)
__global__ void vt0_k(const float* __restrict__ e, const float* __restrict__ cm, float* __restrict__ Vt){
    int i=blockIdx.x*blockDim.x+threadIdx.x;
    if(i<Bsz*Ssz*Dsz) Vt[i]=e[i]-cm[i&(Dsz-1)];
}

// in-place row softmax of bf16 R (rows of length S=1024), 128 threads x 8 elems
__global__ void softmax_rows_bf_k(__nv_bfloat16* __restrict__ R){
    __nv_bfloat16* p=R+(size_t)blockIdx.x*Ssz;
    int t=threadIdx.x;   // 128
    uint4 u=*(uint4*)(p+t*8);
    __nv_bfloat162* hp=(__nv_bfloat162*)&u;
    float v[8];
    #pragma unroll
    for(int i=0;i<4;i++){ v[2*i]=__bfloat162float(hp[i].x); v[2*i+1]=__bfloat162float(hp[i].y); }
    float mx=v[0];
    #pragma unroll
    for(int i=1;i<8;i++) mx=fmaxf(mx,v[i]);
    #pragma unroll
    for(int o=16;o;o>>=1) mx=fmaxf(mx,__shfl_xor_sync(~0u,mx,o));
    __shared__ float sm[4], ss[4];
    if((t&31)==0) sm[t>>5]=mx;
    __syncthreads();
    float m2=fmaxf(fmaxf(sm[0],sm[1]),fmaxf(sm[2],sm[3]));
    float s=0;
    #pragma unroll
    for(int i=0;i<8;i++){ v[i]=__expf(v[i]-m2); s+=v[i]; }
    #pragma unroll
    for(int o=16;o;o>>=1) s+=__shfl_xor_sync(~0u,s,o);
    if((t&31)==0) ss[t>>5]=s;
    __syncthreads();
    float inv=1.f/(ss[0]+ss[1]+ss[2]+ss[3]);
    #pragma unroll
    for(int i=0;i<4;i++){
        hp[i].x=__float2bfloat16(v[2*i]*inv);
        hp[i].y=__float2bfloat16(v[2*i+1]*inv);
    }
    *(uint4*)(p+t*8)=u;
}

// rsum partials: rsP[c][b][s] = sum over v-chunk c of R[b,v,s]  (bf16 R)
__global__ void colsum_k(const __nv_bfloat16* __restrict__ R, float* __restrict__ rsP){
    int s=blockIdx.x*blockDim.x+threadIdx.x;
    int b=blockIdx.y, c=blockIdx.z;
    const int rows=Vsz/CSCH;
    const __nv_bfloat16* p=R+(size_t)b*Vsz*Ssz+(size_t)c*rows*Ssz+s;
    float acc=0;
    for(int v=0;v<rows;v++) acc+=__bfloat162float(p[(size_t)v*Ssz]);
    rsP[(size_t)c*Bsz*Ssz+b*Ssz+s]=acc;
}

// iteration 1: Vt = e - (sum_ks exP)/(sum_c rsP)
__global__ void vt1_k(const float* __restrict__ e, const float* __restrict__ exP,
                      const float* __restrict__ rsP, float* __restrict__ Vt){
    int i=blockIdx.x*blockDim.x+threadIdx.x;
    if(i>=Bsz*Ssz*Dsz) return;
    int d=i&(Dsz-1), s=(i>>9)&(Ssz-1), b=i>>19;
    float ex=0;
    #pragma unroll
    for(int c=0;c<KS;c++) ex+=exP[((size_t)(b*KS+c))*Ssz*Dsz+(size_t)s*Dsz+d];
    float rs=0;
    #pragma unroll
    for(int c=0;c<CSCH;c++) rs+=rsP[(size_t)c*Bsz*Ssz+b*Ssz+s];
    Vt[i]=e[i]-ex/rs;
}

// final: out[b,v] = oln[b,:] . wte[v,:]   (one warp per v, both batches)
__global__ void final_logits_k(const float* __restrict__ oln, const float* __restrict__ wte,
                               float* __restrict__ out){
    int gw=(blockIdx.x*blockDim.x+threadIdx.x)>>5;
    int lane=threadIdx.x&31;
    if(gw>=Vsz) return;
    const float* wr=wte+(size_t)gw*Dsz;
    #pragma unroll
    for(int b=0;b<Bsz;b++){
        float s=0;
        for(int k=lane*4;k<Dsz;k+=128){
            float4 w4=*(const float4*)(wr+k);
            float4 x4=*(const float4*)(oln+b*Dsz+k);
            s+=w4.x*x4.x+w4.y*x4.y+w4.z*x4.z+w4.w*x4.w;
        }
        #pragma unroll
        for(int o=16;o;o>>=1) s+=__shfl_xor_sync(~0u,s,o);
        if(lane==0) out[b*Vsz+gw]=s;
    }
}

// ---------------- orchestration ----------------
extern "C" void kernel_launch(void* const* d_in, const int* in_sizes, int n_in,
                              void* d_out, int out_size)
{
    const int*   x     =(const int*)  d_in[0];
    const float* wte   =(const float*)d_in[1];
    const float* wpe   =(const float*)d_in[2];
    const float* ln_e  =(const float*)d_in[3];
    const float* ln_p  =(const float*)d_in[4];
    const float* ln_f  =(const float*)d_in[5];
    const float* ln_mlp=(const float*)d_in[6];
    const float* Wq    =(const float*)d_in[7];
    const float* Wk    =(const float*)d_in[8];
    const float* Wo    =(const float*)d_in[9];
    const float* w1    =(const float*)d_in[10];
    const float* w2    =(const float*)d_in[11];
    float* out=(float*)d_out;

    float *e,*p,*Aq,*Bk,*krn,*fk,*Vt,*attn,*hln,*act,*exP,*rsP,*cmP,*cm,*oln;
    __nv_bfloat16 *R,*wteh,*fkh;
    cudaGetSymbolAddress((void**)&e,   d_e);
    cudaGetSymbolAddress((void**)&p,   d_p);
    cudaGetSymbolAddress((void**)&Aq,  d_Aq);
    cudaGetSymbolAddress((void**)&Bk,  d_Bk);
    cudaGetSymbolAddress((void**)&krn, d_krn);
    cudaGetSymbolAddress((void**)&fk,  d_fk);
    cudaGetSymbolAddress((void**)&Vt,  d_Vt);
    cudaGetSymbolAddress((void**)&attn,d_attn);
    cudaGetSymbolAddress((void**)&hln, d_hln);
    cudaGetSymbolAddress((void**)&act, d_act);
    cudaGetSymbolAddress((void**)&R,   d_R);
    cudaGetSymbolAddress((void**)&wteh,d_wteh);
    cudaGetSymbolAddress((void**)&fkh, d_fkh);
    cudaGetSymbolAddress((void**)&exP, d_exP);
    cudaGetSymbolAddress((void**)&rsP, d_rsP);
    cudaGetSymbolAddress((void**)&cmP, d_cmP);
    cudaGetSymbolAddress((void**)&cm,  d_cm);
    cudaGetSymbolAddress((void**)&oln, d_oln);

    const float invsqD = 1.0f/sqrtf((float)Dsz);

    // raise dynamic smem limits (idempotent)
    cudaFuncSetAttribute(mma_k<false,true ,1,1,false,false,false,EPI_KRN  ,32>, cudaFuncAttributeMaxDynamicSharedMemorySize, smem_bytes<false,true ,1,1,32>());
    cudaFuncSetAttribute(mma_k<false,true ,0,0,true ,true ,true ,EPI_STORE,32>, cudaFuncAttributeMaxDynamicSharedMemorySize, smem_bytes<false,true ,0,0,32>());
    cudaFuncSetAttribute(mma_k<true ,false,0,0,true ,true ,false,EPI_STORE,32>, cudaFuncAttributeMaxDynamicSharedMemorySize, smem_bytes<true ,false,0,0,32>());
    cudaFuncSetAttribute(mma_k<false,false,1,1,false,false,false,EPI_STORE,32>, cudaFuncAttributeMaxDynamicSharedMemorySize, smem_bytes<false,false,1,1,32>());
    cudaFuncSetAttribute(mma_k<false,true ,1,1,false,false,false,EPI_ADD  ,32>, cudaFuncAttributeMaxDynamicSharedMemorySize, smem_bytes<false,true ,1,1,32>());
    cudaFuncSetAttribute(mma_k<false,true ,1,1,false,false,false,EPI_GELU ,32>, cudaFuncAttributeMaxDynamicSharedMemorySize, smem_bytes<false,true ,1,1,32>());

    // embeddings + positional LN + one-time wte bf16 conversion
    ln_rows_k<<<Bsz*Ssz,128>>>(wte, x,       ln_e, e, 0, 1);
    ln_rows_k<<<Ssz+1,  128>>>(wpe, nullptr, ln_p, p, 0, 1);
    qk_prep_k<<<(Hsz*Ssz*Dsz+255)/256,256>>>(p, Wq, Wk, Aq, Bk);
    colmean_part_k<<<CMCH,Dsz>>>(wte, cmP);
    colmean_red_k<<<1,Dsz>>>(cmP, cm);
    f2bf_k<<<(Vsz*Dsz/4+255)/256,256>>>(wte, wteh, Vsz*Dsz);

    // krn[h,s,t] = (Aq[h,s,:].Bk[h,t,:]) / sqrt(D) / (s+1), causal-masked  [split-2]
    mma_k<false,true,1,1,false,false,false,EPI_KRN,32><<<dim3(Ssz/128,Ssz/128,Hsz),256,smem_bytes<false,true,1,1,32>()>>>(
        Ssz,Ssz,Dsz, Aq,Bk,krn, Dsz,Dsz,Ssz,
        Hsz, 0,(ll)Ssz*Dsz, 0,(ll)Ssz*Dsz, 0,(ll)Ssz*Ssz, 1, 0, invsqD);

    zero_k<<<(Bsz*Ssz*Dsz+255)/256,256>>>(fk, Bsz*Ssz*Dsz);

    for(int it=0; it<2; it++){
        if(it==0){
            vt0_k<<<(Bsz*Ssz*Dsz+255)/256,256>>>(e, cm, Vt);
        }else{
            // fk -> bf16
            f2bf_k<<<(Bsz*Ssz*Dsz/4+255)/256,256>>>(fk, fkh, Bsz*Ssz*Dsz);
            // logits R[b,v,s] = wte[v,:] . fk[b,s,:]   [pure bf16, BK=32, bf16 out]
            mma_k<false,true,0,0,true,true,true,EPI_STORE,32><<<dim3(Ssz/128,Vsz/128,Bsz),256,smem_bytes<false,true,0,0,32>()>>>(
                Vsz,Ssz,Dsz, wteh,fkh,R, Dsz,Dsz,Ssz,
                1, 0,0, (ll)Ssz*Dsz,0, (ll)Vsz*Ssz,0, 1, 0, 0.f);
            softmax_rows_bf_k<<<Bsz*Vsz,128>>>(R);
            colsum_k<<<dim3(Ssz/256,Bsz,CSCH),256>>>(R, rsP);
            // ex_wte[b,s,d] = sum_v R[b,v,s]*wte[v,d]   [pure bf16, BK=32, split-K=8]
            mma_k<true,false,0,0,true,true,false,EPI_STORE,32><<<dim3(Dsz/128,Ssz/128,Bsz*KS),256,smem_bytes<true,false,0,0,32>()>>>(
                Ssz,Dsz,Vsz, R,wteh,exP, Ssz,Dsz,Dsz,
                KS, (ll)Vsz*Ssz,0, 0,0, (ll)KS*Ssz*Dsz,(ll)Ssz*Dsz, KS, 0, 0.f);
            vt1_k<<<(Bsz*Ssz*Dsz+255)/256,256>>>(e, exP, rsP, Vt);
        }
        // attn[b,s,h*D+d] = sum_t krn[h,s,t]*Vt[b,t,d]  [split-2, causal triK]
        mma_k<false,false,1,1,false,false,false,EPI_STORE,32><<<dim3(Dsz/128,Ssz/128,Bsz*Hsz),256,smem_bytes<false,false,1,1,32>()>>>(
            Ssz,Dsz,Ssz, krn,Vt,attn, Ssz,Dsz,Hsz*Dsz,
            Hsz, 0,(ll)Ssz*Ssz, (ll)Ssz*Dsz,0, (ll)Ssz*Hsz*Dsz,(ll)Dsz, 1, 1, 0.f);
        // fk += attn @ Wo[it]^T  [split-2]
        mma_k<false,true,1,1,false,false,false,EPI_ADD,32><<<dim3(Dsz/128,(Bsz*Ssz)/128,1),256,smem_bytes<false,true,1,1,32>()>>>(
            Bsz*Ssz,Dsz,Hsz*Dsz, attn, Wo+(size_t)it*Dsz*Hsz*Dsz, fk, Hsz*Dsz,Hsz*Dsz,Dsz,
            1, 0,0,0,0,0,0, 1, 0, 0.f);
        // MLP  [split-2]
        ln_rows_k<<<Bsz*Ssz,128>>>(fk, nullptr, ln_mlp, hln, 0, 1);
        mma_k<false,true,1,1,false,false,false,EPI_GELU,32><<<dim3(DFFsz/128,(Bsz*Ssz)/128,1),256,smem_bytes<false,true,1,1,32>()>>>(
            Bsz*Ssz,DFFsz,Dsz, hln,w1,act, Dsz,Dsz,DFFsz,
            1, 0,0,0,0,0,0, 1, 0, 0.f);
        mma_k<false,true,1,1,false,false,false,EPI_ADD,32><<<dim3(Dsz/128,(Bsz*Ssz)/128,1),256,smem_bytes<false,true,1,1,32>()>>>(
            Bsz*Ssz,Dsz,DFFsz, act,w2,fk, DFFsz,DFFsz,Dsz,
            1, 0,0,0,0,0,0, 1, 0, 0.f);
    }

    // final LN of last token per batch, then logits vs wte
    ln_rows_k<<<Bsz,128>>>(fk, nullptr, ln_f, oln, Ssz-1, Ssz);
    final_logits_k<<<(Vsz*32+255)/256,256>>>(oln, wte, out);
}

// round 17
// speedup vs baseline: 1.4127x; 1.0337x over previous
#include <cuda_runtime.h>
#include <cuda_bf16.h>
#include <math.h>

// Problem constants
#define Bsz   2
#define Ssz   1024
#define Dsz   512
#define Hsz   8
#define Vsz   32000
#define DFFsz 2048
#define KS    8      // split-K factor for ex_wte GEMM (32000/8=4000, 4000/32=125)
#define CSCH  16     // chunks for column-sum of R
#define CMCH  128    // chunks for column-mean of wte

typedef long long ll;

// ---------------- device scratch (no allocations allowed) ----------------
__device__ float d_e  [Bsz*Ssz*Dsz];
__device__ float d_p  [(Ssz+1)*Dsz];
__device__ float d_Aq [Hsz*Ssz*Dsz];
__device__ float d_Bk [Hsz*Ssz*Dsz];
__device__ float d_krn[(size_t)Hsz*Ssz*Ssz];
__device__ float d_fk [Bsz*Ssz*Dsz];
__device__ float d_Vt [Bsz*Ssz*Dsz];
__device__ float d_attn[(size_t)Bsz*Ssz*Hsz*Dsz];
__device__ float d_hln[Bsz*Ssz*Dsz];
__device__ float d_act[Bsz*Ssz*DFFsz];
__device__ __nv_bfloat16 d_R[(size_t)Bsz*Vsz*Ssz];   // 131 MB (bf16)
__device__ __nv_bfloat16 d_wteh[(size_t)Vsz*Dsz];    // 33 MB  (bf16 wte)
__device__ __nv_bfloat16 d_fkh[Bsz*Ssz*Dsz];         // 4 MB   (bf16 fk)
__device__ float d_exP[(size_t)Bsz*KS*Ssz*Dsz];
__device__ float d_rsP[CSCH*Bsz*Ssz];
__device__ float d_cmP[CMCH*Dsz];
__device__ float d_cm [Dsz];
__device__ float d_oln[Bsz*Dsz];

enum { EPI_STORE=0, EPI_ADD=1, EPI_GELU=2, EPI_KRN=3 };

// ---------------- ldmatrix / mma / cp.async wrappers ----------------
__device__ __forceinline__ void ldsm4(unsigned &r0,unsigned &r1,unsigned &r2,unsigned &r3,unsigned a){
    asm volatile("ldmatrix.sync.aligned.m8n8.x4.shared.b16 {%0,%1,%2,%3},[%4];"
        :"=r"(r0),"=r"(r1),"=r"(r2),"=r"(r3):"r"(a));
}
__device__ __forceinline__ void ldsm4t(unsigned &r0,unsigned &r1,unsigned &r2,unsigned &r3,unsigned a){
    asm volatile("ldmatrix.sync.aligned.m8n8.x4.trans.shared.b16 {%0,%1,%2,%3},[%4];"
        :"=r"(r0),"=r"(r1),"=r"(r2),"=r"(r3):"r"(a));
}
__device__ __forceinline__ void ldsm2(unsigned &r0,unsigned &r1,unsigned a){
    asm volatile("ldmatrix.sync.aligned.m8n8.x2.shared.b16 {%0,%1},[%2];"
        :"=r"(r0),"=r"(r1):"r"(a));
}
__device__ __forceinline__ void ldsm2t(unsigned &r0,unsigned &r1,unsigned a){
    asm volatile("ldmatrix.sync.aligned.m8n8.x2.trans.shared.b16 {%0,%1},[%2];"
        :"=r"(r0),"=r"(r1):"r"(a));
}
__device__ __forceinline__ void mma16816(float* c,const unsigned* a,const unsigned* b){
    asm volatile("mma.sync.aligned.m16n8k16.row.col.f32.bf16.bf16.f32 "
        "{%0,%1,%2,%3},{%4,%5,%6,%7},{%8,%9},{%0,%1,%2,%3};"
        : "+f"(c[0]),"+f"(c[1]),"+f"(c[2]),"+f"(c[3])
        : "r"(a[0]),"r"(a[1]),"r"(a[2]),"r"(a[3]),"r"(b[0]),"r"(b[1]));
}
__device__ __forceinline__ void cpasync16(unsigned smem, const void* g){
    asm volatile("cp.async.cg.shared.global [%0], [%1], 16;" :: "r"(smem), "l"(g));
}
#define CP_COMMIT() asm volatile("cp.async.commit_group;" ::: "memory")
#define CP_WAIT2()  asm volatile("cp.async.wait_group 2;"  ::: "memory")

// dynamic smem bytes: 2 stages x ((1+SA)*A + (1+SB)*B) bf16 tiles
template<bool TA,bool TB,int SA,int SB,int BKT> constexpr int smem_bytes(){
    constexpr int ASZ=(TA?BKT:128)*(TA?136:BKT+8);
    constexpr int BSZ=(TB?128:BKT)*(TB?BKT+8:136);
    return 2*((1+SA)*ASZ+(1+SB)*BSZ)*2;
}
// async kernel smem: 4 stages x (A + B), K-padded rows use +24 (112B: 16B-aligned, conflict-free)
template<bool TA,bool TB> constexpr int smem_async(){
    constexpr int ASZ=(TA?32:128)*(TA?136:56);
    constexpr int BSZ=(TB?128:32)*(TB?56:136);
    return 4*(ASZ+BSZ)*2;
}

// ---------------- pure-bf16 tensor-core GEMM, 4-stage cp.async pipeline ----
// Both operands bf16 in gmem. C(MxN)=A*B. TA: A stored KxM. TB: B stored NxK.
// CBF: C written bf16 (else fp32 EPI_STORE). Batched via blockIdx.z.
// Ksplit>1: z2 picks K-slice. 256 thr = 8 warps (2Mx4N), warp tile 64x32.
template<bool TA,bool TB,bool CBF>
__global__ void __launch_bounds__(256,1)
mma_bf_k(int M,int N,int K,
      const __nv_bfloat16* __restrict__ A,const __nv_bfloat16* __restrict__ B,void* __restrict__ Cv,
      int lda,int ldb,int ldc,
      int Z2, ll sA1, ll sA2, ll sB1, ll sB2, ll sC1, ll sC2,
      int Ksplit)
{
    constexpr int BM=128, BN=128, BK=32;
    constexpr int ACols = TA ? BM+8 : BK+24;   // 136 (272B) / 56 (112B)
    constexpr int BCols = TB ? BK+24 : BN+8;
    constexpr int ARows = TA ? BK : BM;
    constexpr int BRows = TB ? BN : BK;
    constexpr int ASZ = ARows*ACols;
    constexpr int BSZ = BRows*BCols;
    constexpr int STG = ASZ+BSZ;

    extern __shared__ __align__(16) __nv_bfloat16 S[];

    const int z=blockIdx.z, z1=z/Z2, z2=z%Z2;
    A += z1*sA1 + z2*sA2;
    B += z1*sB1 + z2*sB2;
    float*         Cf=(float*)Cv + z1*sC1 + z2*sC2;
    __nv_bfloat16* Cb=(__nv_bfloat16*)Cv + z1*sC1 + z2*sC2;
    const int m0=blockIdx.y*BM, n0=blockIdx.x*BN;

    int kbeg=0, kend=K;
    if (Ksplit>1){ int kc=K/Ksplit; kbeg=z2*kc; kend=kbeg+kc; }

    const int tid=threadIdx.x;
    const int lane=tid&31, wid=tid>>5;
    const int wm=wid&1, wn=wid>>1;
    const int gid=lane>>2, tig=lane&3;

    int a_m, a_k;
    if(!TA){ a_m=(lane&7)+((lane&8)?8:0); a_k=(lane&16)?8:0; }
    else   { a_k=(lane&7)+((lane&16)?8:0); a_m=(lane&8)?8:0; }
    const int l16=lane&15;
    int b_n, b_k;
    if(TB){ b_n=l16&7;                 b_k=(l16&8)?8:0; }
    else  { b_k=(l16&7)+((l16&8)?8:0); b_n=0; }

    const unsigned sbase=(unsigned)__cvta_generic_to_shared(S);

    float acc[4][4][4];
    #pragma unroll
    for(int i=0;i<4;i++)
        #pragma unroll
        for(int j=0;j<4;j++)
            #pragma unroll
            for(int r=0;r<4;r++) acc[i][j][r]=0.f;

    // issue one stage: 2 x 16B cp.async per thread for A, 2 for B
    auto issue_stage=[&](int st,int kk0){
        unsigned abase = sbase + (unsigned)(st*STG)*2;
        unsigned bbase = abase + (unsigned)ASZ*2;
        #pragma unroll
        for(int u=0;u<2;u++){
            int t=tid+u*256;
            if(!TA){ int row=t>>2, kq=(t&3)*8;
                     cpasync16(abase+(row*ACols+kq)*2, A+(size_t)(m0+row)*lda+kk0+kq); }
            else   { int row=t>>4, mq=(t&15)*8;
                     cpasync16(abase+(row*ACols+mq)*2, A+(size_t)(kk0+row)*lda+m0+mq); }
        }
        #pragma unroll
        for(int u=0;u<2;u++){
            int t=tid+u*256;
            if(TB){ int row=t>>2, kq=(t&3)*8;
                    cpasync16(bbase+(row*BCols+kq)*2, B+(size_t)(n0+row)*ldb+kk0+kq); }
            else  { int row=t>>4, nq=(t&15)*8;
                    cpasync16(bbase+(row*BCols+nq)*2, B+(size_t)(kk0+row)*ldb+n0+nq); }
        }
    };
    auto compute_stage=[&](int st){
        const unsigned aHb = sbase + (unsigned)(st*STG)*2;
        const unsigned bHb = aHb + (unsigned)ASZ*2;
        #pragma unroll
        for(int kk=0;kk<BK;kk+=16){
            unsigned ah[4][4];
            #pragma unroll
            for(int i=0;i<4;i++){
                int mi=wm*64+i*16;
                int off = !TA ? (mi+a_m)*ACols + kk + a_k
                              : (kk+a_k)*ACols + mi + a_m;
                if(!TA) ldsm4 (ah[i][0],ah[i][1],ah[i][2],ah[i][3], aHb+off*2);
                else    ldsm4t(ah[i][0],ah[i][1],ah[i][2],ah[i][3], aHb+off*2);
            }
            #pragma unroll
            for(int j=0;j<4;j++){
                int nj=wn*32+j*8;
                unsigned bh[2];
                int off = TB ? (nj+b_n)*BCols + kk + b_k
                             : (kk+b_k)*BCols + nj;
                if(TB) ldsm2 (bh[0],bh[1], bHb+off*2);
                else   ldsm2t(bh[0],bh[1], bHb+off*2);
                #pragma unroll
                for(int i=0;i<4;i++)
                    mma16816(acc[i][j], ah[i], bh);
            }
        }
    };

    // ---- 4-stage pipeline ----
    const int nIter=(kend-kbeg)/BK;
    int pre = nIter<3 ? nIter : 3;
    for(int s=0;s<pre;s++){ issue_stage(s, kbeg+s*BK); CP_COMMIT(); }
    for(int it=0; it<nIter; it++){
        CP_WAIT2();
        __syncthreads();
        compute_stage(it&3);
        __syncthreads();
        int nx=it+3;
        if(nx<nIter){ issue_stage(nx&3, kbeg+nx*BK); CP_COMMIT(); }
    }

    // epilogue
    #pragma unroll
    for(int i=0;i<4;i++){
        int m = m0 + wm*64 + i*16 + gid;
        #pragma unroll
        for(int j=0;j<4;j++){
            int n = n0 + wn*32 + j*8 + tig*2;
            if(CBF){
                __nv_bfloat16* r0 = Cb + (size_t)m*ldc + n;
                __nv_bfloat16* r1 = Cb + (size_t)(m+8)*ldc + n;
                r0[0]=__float2bfloat16(acc[i][j][0]); r0[1]=__float2bfloat16(acc[i][j][1]);
                r1[0]=__float2bfloat16(acc[i][j][2]); r1[1]=__float2bfloat16(acc[i][j][3]);
            }else{
                float* r0 = Cf + (size_t)m*ldc + n;
                float* r1 = Cf + (size_t)(m+8)*ldc + n;
                r0[0]=acc[i][j][0]; r0[1]=acc[i][j][1];
                r1[0]=acc[i][j][2]; r1[1]=acc[i][j][3];
            }
        }
    }
}

// ---------------- bf16 tensor-core GEMM, tiered precision, double-buffered ----
// (split-2 paths; unchanged from round-15 baseline)
template<bool TA,bool TB,int SA,int SB,bool ABF,bool BBF,bool CBF,int EPI,int BKT>
__global__ void __launch_bounds__(256,1)
mma_k(int M,int N,int K,
      const void* __restrict__ Av,const void* __restrict__ Bv,void* __restrict__ Cv,
      int lda,int ldb,int ldc,
      int Z2, ll sA1, ll sA2, ll sB1, ll sB2, ll sC1, ll sC2,
      int Ksplit, int triK, float p0)
{
    constexpr int BM=128, BN=128, BK=BKT;
    constexpr int ACols = TA ? BM+8 : BK+8;
    constexpr int BCols = TB ? BK+8 : BN+8;
    constexpr int ARows = TA ? BK : BM;
    constexpr int BRows = TB ? BN : BK;
    constexpr int ASZ = ARows*ACols;
    constexpr int BSZ = BRows*BCols;
    constexpr int STG = (1+SA)*ASZ + (1+SB)*BSZ;
    constexpr int NAF = BM*BK/1024;
    constexpr int NBF = BN*BK/1024;

    extern __shared__ __align__(16) __nv_bfloat16 S[];

    const int z=blockIdx.z, z1=z/Z2, z2=z%Z2;
    const float* Af=(const float*)Av + z1*sA1 + z2*sA2;
    const float* Bf=(const float*)Bv + z1*sB1 + z2*sB2;
    float* Cf=(float*)Cv + z1*sC1 + z2*sC2;
    const int m0=blockIdx.y*BM, n0=blockIdx.x*BN;

    int kbeg=0, kend=K;
    if (Ksplit>1){ int kc=K/Ksplit; kbeg=z2*kc; kend=kbeg+kc; }
    if (triK && kend > m0+BM) kend = m0+BM;
    if (EPI==EPI_KRN && n0 >= m0+BM) kend = kbeg;

    const int tid=threadIdx.x;
    const int lane=tid&31, wid=tid>>5;
    const int wm=wid&1, wn=wid>>1;
    const int gid=lane>>2, tig=lane&3;

    int a_m, a_k;
    if(!TA){ a_m=(lane&7)+((lane&8)?8:0); a_k=(lane&16)?8:0; }
    else   { a_k=(lane&7)+((lane&16)?8:0); a_m=(lane&8)?8:0; }
    const int l16=lane&15;
    int b_n, b_k;
    if(TB){ b_n=l16&7;                 b_k=(l16&8)?8:0; }
    else  { b_k=(l16&7)+((l16&8)?8:0); b_n=0; }

    const unsigned sbase=(unsigned)__cvta_generic_to_shared(S);

    float acc[4][4][4];
    #pragma unroll
    for(int i=0;i<4;i++)
        #pragma unroll
        for(int j=0;j<4;j++)
            #pragma unroll
            for(int r=0;r<4;r++) acc[i][j][r]=0.f;

    float4 ra[NAF];
    float4 rb[NBF];

    auto load_regs=[&](int kk0){
        #pragma unroll
        for(int u=0;u<NAF;u++){
            int t=tid+u*256;
            if(!TA){ int row=t/(BK/4), kq=(t%(BK/4))*4; ra[u]=*(const float4*)(Af+(size_t)(m0+row)*lda+kk0+kq); }
            else   { int kk=t/(BM/4), mq=(t%(BM/4))*4; ra[u]=*(const float4*)(Af+(size_t)(kk0+kk)*lda+m0+mq); }
        }
        #pragma unroll
        for(int u=0;u<NBF;u++){
            int t=tid+u*256;
            if(TB) { int row=t/(BK/4), kq=(t%(BK/4))*4; rb[u]=*(const float4*)(Bf+(size_t)(n0+row)*ldb+kk0+kq); }
            else   { int kk=t/(BN/4), nq=(t%(BN/4))*4; rb[u]=*(const float4*)(Bf+(size_t)(kk0+kk)*ldb+n0+nq); }
        }
    };
    auto store_stage=[&](int s){
        __nv_bfloat16* Ah = S + s*STG;
        __nv_bfloat16* Al = Ah + ASZ;
        __nv_bfloat16* Bh = Ah + (1+SA)*ASZ;
        __nv_bfloat16* Bl = Bh + BSZ;
        #pragma unroll
        for(int u=0;u<NAF;u++){
            int t=tid+u*256;
            float f[4]={ra[u].x,ra[u].y,ra[u].z,ra[u].w};
            __nv_bfloat16 h[4], l[4];
            #pragma unroll
            for(int q=0;q<4;q++){ h[q]=__float2bfloat16(f[q]); if(SA) l[q]=__float2bfloat16(f[q]-__bfloat162float(h[q])); }
            int off;
            if(!TA){ int row=t/(BK/4), kq=(t%(BK/4))*4; off=row*ACols+kq; }
            else   { int kk=t/(BM/4), mq=(t%(BM/4))*4; off=kk*ACols+mq; }
            __nv_bfloat162 pp;
            pp.x=h[0]; pp.y=h[1]; *(__nv_bfloat162*)(Ah+off)=pp;
            pp.x=h[2]; pp.y=h[3]; *(__nv_bfloat162*)(Ah+off+2)=pp;
            if(SA){
                pp.x=l[0]; pp.y=l[1]; *(__nv_bfloat162*)(Al+off)=pp;
                pp.x=l[2]; pp.y=l[3]; *(__nv_bfloat162*)(Al+off+2)=pp;
            }
        }
        #pragma unroll
        for(int u=0;u<NBF;u++){
            int t=tid+u*256;
            float g[4]={rb[u].x,rb[u].y,rb[u].z,rb[u].w};
            __nv_bfloat16 h[4], l[4];
            #pragma unroll
            for(int q=0;q<4;q++){ h[q]=__float2bfloat16(g[q]); if(SB) l[q]=__float2bfloat16(g[q]-__bfloat162float(h[q])); }
            int off;
            if(TB){ int row=t/(BK/4), kq=(t%(BK/4))*4; off=row*BCols+kq; }
            else  { int kk=t/(BN/4), nq=(t%(BN/4))*4; off=kk*BCols+nq; }
            __nv_bfloat162 pp;
            pp.x=h[0]; pp.y=h[1]; *(__nv_bfloat162*)(Bh+off)=pp;
            pp.x=h[2]; pp.y=h[3]; *(__nv_bfloat162*)(Bh+off+2)=pp;
            if(SB){
                pp.x=l[0]; pp.y=l[1]; *(__nv_bfloat162*)(Bl+off)=pp;
                pp.x=l[2]; pp.y=l[3]; *(__nv_bfloat162*)(Bl+off+2)=pp;
            }
        }
    };
    auto compute_stage=[&](int s){
        const unsigned aHb = sbase + (s*STG)*2;
        const unsigned aLb = aHb + ASZ*2;
        const unsigned bHb = aHb + (1+SA)*ASZ*2;
        const unsigned bLb = bHb + BSZ*2;
        #pragma unroll
        for(int kk=0;kk<BK;kk+=16){
            unsigned ah[4][4], al[4][4];
            #pragma unroll
            for(int i=0;i<4;i++){
                int mi=wm*64+i*16;
                int off = !TA ? (mi+a_m)*ACols + kk + a_k
                              : (kk+a_k)*ACols + mi + a_m;
                if(!TA){ ldsm4 (ah[i][0],ah[i][1],ah[i][2],ah[i][3], aHb+off*2);
                         if(SA) ldsm4 (al[i][0],al[i][1],al[i][2],al[i][3], aLb+off*2); }
                else   { ldsm4t(ah[i][0],ah[i][1],ah[i][2],ah[i][3], aHb+off*2);
                         if(SA) ldsm4t(al[i][0],al[i][1],al[i][2],al[i][3], aLb+off*2); }
            }
            #pragma unroll
            for(int j=0;j<4;j++){
                int nj=wn*32+j*8;
                unsigned bh[2], bl[2];
                int off = TB ? (nj+b_n)*BCols + kk + b_k
                             : (kk+b_k)*BCols + nj;
                if(TB){ ldsm2 (bh[0],bh[1], bHb+off*2);
                        if(SB) ldsm2 (bl[0],bl[1], bLb+off*2); }
                else  { ldsm2t(bh[0],bh[1], bHb+off*2);
                        if(SB) ldsm2t(bl[0],bl[1], bLb+off*2); }
                #pragma unroll
                for(int i=0;i<4;i++){
                    mma16816(acc[i][j], ah[i], bh);
                    if(SB) mma16816(acc[i][j], ah[i], bl);
                    if(SA) mma16816(acc[i][j], al[i], bh);
                }
            }
        }
    };

    const int nIter=(kend-kbeg)/BK;
    if(nIter>0){
        load_regs(kbeg);
        store_stage(0);
        __syncthreads();
        for(int it=0; it<nIter; it++){
            if(it+1<nIter) load_regs(kbeg+(it+1)*BK);
            compute_stage(it&1);
            if(it+1<nIter) store_stage((it+1)&1);
            __syncthreads();
        }
    }

    #pragma unroll
    for(int i=0;i<4;i++){
        int m = m0 + wm*64 + i*16 + gid;
        #pragma unroll
        for(int j=0;j<4;j++){
            int n = n0 + wn*32 + j*8 + tig*2;
            float v0=acc[i][j][0], v1=acc[i][j][1], v2=acc[i][j][2], v3=acc[i][j][3];
            float* r0 = Cf + (size_t)m*ldc + n;
            float* r1 = Cf + (size_t)(m+8)*ldc + n;
            if(EPI==EPI_STORE){ r0[0]=v0; r0[1]=v1; r1[0]=v2; r1[1]=v3; }
            else if(EPI==EPI_ADD){ r0[0]+=v0; r0[1]+=v1; r1[0]+=v2; r1[1]+=v3; }
            else if(EPI==EPI_GELU){
                r0[0]=0.5f*v0*(1.0f+erff(v0*0.70710678118f));
                r0[1]=0.5f*v1*(1.0f+erff(v1*0.70710678118f));
                r1[0]=0.5f*v2*(1.0f+erff(v2*0.70710678118f));
                r1[1]=0.5f*v3*(1.0f+erff(v3*0.70710678118f));
            }else{ // EPI_KRN
                r0[0]=(n  <=m  )? v0*(p0/(float)(m+1))   : 0.0f;
                r0[1]=(n+1<=m  )? v1*(p0/(float)(m+1))   : 0.0f;
                r1[0]=(n  <=m+8)? v2*(p0/(float)(m+9))   : 0.0f;
                r1[1]=(n+1<=m+8)? v3*(p0/(float)(m+9))   : 0.0f;
            }
        }
    }
}

// fp32 -> bf16 bulk convert (n multiple of 4)
__global__ void f2bf_k(const float* __restrict__ in, __nv_bfloat16* __restrict__ out, int n){
    int i=(blockIdx.x*blockDim.x+threadIdx.x)*4;
    if(i<n){
        float4 v=*(const float4*)(in+i);
        __nv_bfloat162 a,b;
        a.x=__float2bfloat16(v.x); a.y=__float2bfloat16(v.y);
        b.x=__float2bfloat16(v.z); b.y=__float2bfloat16(v.w);
        *(__nv_bfloat162*)(out+i)=a;
        *(__nv_bfloat162*)(out+i+2)=b;
    }
}

// ---------------- layernorm over D=512 rows ----------------
__global__ void ln_rows_k(const float* __restrict__ in, const int* __restrict__ idx,
                          const float* __restrict__ w, float* __restrict__ out,
                          int rowoff, int rowstride)
{
    int r=blockIdx.x, t=threadIdx.x;
    long src = idx ? (long)idx[r] : ((long)r*rowstride + rowoff);
    const float* x = in + src*(long)Dsz;
    float4 v=*(const float4*)(x+t*4);
    float s=v.x+v.y+v.z+v.w;
    float sq=v.x*v.x+v.y*v.y+v.z*v.z+v.w*v.w;
    #pragma unroll
    for(int o=16;o;o>>=1){ s+=__shfl_xor_sync(~0u,s,o); sq+=__shfl_xor_sync(~0u,sq,o); }
    __shared__ float sa[4], sb[4];
    if((t&31)==0){ sa[t>>5]=s; sb[t>>5]=sq; }
    __syncthreads();
    s=sa[0]+sa[1]+sa[2]+sa[3]; sq=sb[0]+sb[1]+sb[2]+sb[3];
    float mu=s*(1.f/Dsz), var=sq*(1.f/Dsz)-mu*mu;
    float rs=rsqrtf(var+1e-5f);
    float4 wv=*(const float4*)(w+t*4);
    float4 o4;
    o4.x=(v.x-mu)*rs*wv.x; o4.y=(v.y-mu)*rs*wv.y;
    o4.z=(v.z-mu)*rs*wv.z; o4.w=(v.w-mu)*rs*wv.w;
    *(float4*)(out+(size_t)r*Dsz+t*4)=o4;
}

// Aq[h,s,d]=p[s+1,d]*Wq[h,d];  Bk[h,s,d]=p[s,d]*Wk[h,d]
__global__ void qk_prep_k(const float* __restrict__ p, const float* __restrict__ Wq,
                          const float* __restrict__ Wk, float* __restrict__ Aq, float* __restrict__ Bk)
{
    int i=blockIdx.x*blockDim.x+threadIdx.x;
    if(i>=Hsz*Ssz*Dsz) return;
    int d=i%Dsz, s=(i/Dsz)%Ssz, h=i/(Dsz*Ssz);
    Aq[i]=p[(s+1)*Dsz+d]*Wq[h*Dsz+d];
    Bk[i]=p[s*Dsz+d]*Wk[h*Dsz+d];
}

__global__ void colmean_part_k(const float* __restrict__ wte, float* __restrict__ cmP){
    int d=threadIdx.x, c=blockIdx.x;
    const int rows=Vsz/CMCH;
    float s=0;
    for(int v=c*rows; v<(c+1)*rows; v++) s+=wte[(size_t)v*Dsz+d];
    cmP[c*Dsz+d]=s;
}
__global__ void colmean_red_k(const float* __restrict__ cmP, float* __restrict__ cm){
    int d=threadIdx.x; float s=0;
    for(int c=0;c<CMCH;c++) s+=cmP[c*Dsz+d];
    cm[d]=s*(1.0f/Vsz);
}

__global__ void zero_k(float* __restrict__ p, int n){
    int i=blockIdx.x*blockDim.x+threadIdx.x;
    if(i<n) p[i]=0.f;
}

// iteration 0: Vt = e - colmean(wte)
__global__ void vt0_k(const float* __restrict__ e, const float* __restrict__ cm, float* __restrict__ Vt){
    int i=blockIdx.x*blockDim.x+threadIdx.x;
    if(i<Bsz*Ssz*Dsz) Vt[i]=e[i]-cm[i&(Dsz-1)];
}

// in-place row softmax of bf16 R (rows of length S=1024), 128 threads x 8 elems
__global__ void softmax_rows_bf_k(__nv_bfloat16* __restrict__ R){
    __nv_bfloat16* p=R+(size_t)blockIdx.x*Ssz;
    int t=threadIdx.x;   // 128
    uint4 u=*(uint4*)(p+t*8);
    __nv_bfloat162* hp=(__nv_bfloat162*)&u;
    float v[8];
    #pragma unroll
    for(int i=0;i<4;i++){ v[2*i]=__bfloat162float(hp[i].x); v[2*i+1]=__bfloat162float(hp[i].y); }
    float mx=v[0];
    #pragma unroll
    for(int i=1;i<8;i++) mx=fmaxf(mx,v[i]);
    #pragma unroll
    for(int o=16;o;o>>=1) mx=fmaxf(mx,__shfl_xor_sync(~0u,mx,o));
    __shared__ float sm[4], ss[4];
    if((t&31)==0) sm[t>>5]=mx;
    __syncthreads();
    float m2=fmaxf(fmaxf(sm[0],sm[1]),fmaxf(sm[2],sm[3]));
    float s=0;
    #pragma unroll
    for(int i=0;i<8;i++){ v[i]=__expf(v[i]-m2); s+=v[i]; }
    #pragma unroll
    for(int o=16;o;o>>=1) s+=__shfl_xor_sync(~0u,s,o);
    if((t&31)==0) ss[t>>5]=s;
    __syncthreads();
    float inv=1.f/(ss[0]+ss[1]+ss[2]+ss[3]);
    #pragma unroll
    for(int i=0;i<4;i++){
        hp[i].x=__float2bfloat16(v[2*i]*inv);
        hp[i].y=__float2bfloat16(v[2*i+1]*inv);
    }
    *(uint4*)(p+t*8)=u;
}

// rsum partials: rsP[c][b][s] = sum over v-chunk c of R[b,v,s]  (bf16 R)
__global__ void colsum_k(const __nv_bfloat16* __restrict__ R, float* __restrict__ rsP){
    int s=blockIdx.x*blockDim.x+threadIdx.x;
    int b=blockIdx.y, c=blockIdx.z;
    const int rows=Vsz/CSCH;
    const __nv_bfloat16* p=R+(size_t)b*Vsz*Ssz+(size_t)c*rows*Ssz+s;
    float acc=0;
    for(int v=0;v<rows;v++) acc+=__bfloat162float(p[(size_t)v*Ssz]);
    rsP[(size_t)c*Bsz*Ssz+b*Ssz+s]=acc;
}

// iteration 1: Vt = e - (sum_ks exP)/(sum_c rsP)
__global__ void vt1_k(const float* __restrict__ e, const float* __restrict__ exP,
                      const float* __restrict__ rsP, float* __restrict__ Vt){
    int i=blockIdx.x*blockDim.x+threadIdx.x;
    if(i>=Bsz*Ssz*Dsz) return;
    int d=i&(Dsz-1), s=(i>>9)&(Ssz-1), b=i>>19;
    float ex=0;
    #pragma unroll
    for(int c=0;c<KS;c++) ex+=exP[((size_t)(b*KS+c))*Ssz*Dsz+(size_t)s*Dsz+d];
    float rs=0;
    #pragma unroll
    for(int c=0;c<CSCH;c++) rs+=rsP[(size_t)c*Bsz*Ssz+b*Ssz+s];
    Vt[i]=e[i]-ex/rs;
}

// final: out[b,v] = oln[b,:] . wte[v,:]   (one warp per v, both batches)
__global__ void final_logits_k(const float* __restrict__ oln, const float* __restrict__ wte,
                               float* __restrict__ out){
    int gw=(blockIdx.x*blockDim.x+threadIdx.x)>>5;
    int lane=threadIdx.x&31;
    if(gw>=Vsz) return;
    const float* wr=wte+(size_t)gw*Dsz;
    #pragma unroll
    for(int b=0;b<Bsz;b++){
        float s=0;
        for(int k=lane*4;k<Dsz;k+=128){
            float4 w4=*(const float4*)(wr+k);
            float4 x4=*(const float4*)(oln+b*Dsz+k);
            s+=w4.x*x4.x+w4.y*x4.y+w4.z*x4.z+w4.w*x4.w;
        }
        #pragma unroll
        for(int o=16;o;o>>=1) s+=__shfl_xor_sync(~0u,s,o);
        if(lane==0) out[b*Vsz+gw]=s;
    }
}

// ---------------- orchestration ----------------
extern "C" void kernel_launch(void* const* d_in, const int* in_sizes, int n_in,
                              void* d_out, int out_size)
{
    const int*   x     =(const int*)  d_in[0];
    const float* wte   =(const float*)d_in[1];
    const float* wpe   =(const float*)d_in[2];
    const float* ln_e  =(const float*)d_in[3];
    const float* ln_p  =(const float*)d_in[4];
    const float* ln_f  =(const float*)d_in[5];
    const float* ln_mlp=(const float*)d_in[6];
    const float* Wq    =(const float*)d_in[7];
    const float* Wk    =(const float*)d_in[8];
    const float* Wo    =(const float*)d_in[9];
    const float* w1    =(const float*)d_in[10];
    const float* w2    =(const float*)d_in[11];
    float* out=(float*)d_out;

    float *e,*p,*Aq,*Bk,*krn,*fk,*Vt,*attn,*hln,*act,*exP,*rsP,*cmP,*cm,*oln;
    __nv_bfloat16 *R,*wteh,*fkh;
    cudaGetSymbolAddress((void**)&e,   d_e);
    cudaGetSymbolAddress((void**)&p,   d_p);
    cudaGetSymbolAddress((void**)&Aq,  d_Aq);
    cudaGetSymbolAddress((void**)&Bk,  d_Bk);
    cudaGetSymbolAddress((void**)&krn, d_krn);
    cudaGetSymbolAddress((void**)&fk,  d_fk);
    cudaGetSymbolAddress((void**)&Vt,  d_Vt);
    cudaGetSymbolAddress((void**)&attn,d_attn);
    cudaGetSymbolAddress((void**)&hln, d_hln);
    cudaGetSymbolAddress((void**)&act, d_act);
    cudaGetSymbolAddress((void**)&R,   d_R);
    cudaGetSymbolAddress((void**)&wteh,d_wteh);
    cudaGetSymbolAddress((void**)&fkh, d_fkh);
    cudaGetSymbolAddress((void**)&exP, d_exP);
    cudaGetSymbolAddress((void**)&rsP, d_rsP);
    cudaGetSymbolAddress((void**)&cmP, d_cmP);
    cudaGetSymbolAddress((void**)&cm,  d_cm);
    cudaGetSymbolAddress((void**)&oln, d_oln);

    const float invsqD = 1.0f/sqrtf((float)Dsz);

    // raise dynamic smem limits (idempotent)
    cudaFuncSetAttribute(mma_k<false,true ,1,1,false,false,false,EPI_KRN  ,32>, cudaFuncAttributeMaxDynamicSharedMemorySize, smem_bytes<false,true ,1,1,32>());
    cudaFuncSetAttribute(mma_bf_k<false,true ,true >, cudaFuncAttributeMaxDynamicSharedMemorySize, smem_async<false,true >());
    cudaFuncSetAttribute(mma_bf_k<true ,false,false>, cudaFuncAttributeMaxDynamicSharedMemorySize, smem_async<true ,false>());
    cudaFuncSetAttribute(mma_k<false,false,1,1,false,false,false,EPI_STORE,32>, cudaFuncAttributeMaxDynamicSharedMemorySize, smem_bytes<false,false,1,1,32>());
    cudaFuncSetAttribute(mma_k<false,true ,1,1,false,false,false,EPI_ADD  ,32>, cudaFuncAttributeMaxDynamicSharedMemorySize, smem_bytes<false,true ,1,1,32>());
    cudaFuncSetAttribute(mma_k<false,true ,1,1,false,false,false,EPI_GELU ,32>, cudaFuncAttributeMaxDynamicSharedMemorySize, smem_bytes<false,true ,1,1,32>());

    // embeddings + positional LN + one-time wte bf16 conversion
    ln_rows_k<<<Bsz*Ssz,128>>>(wte, x,       ln_e, e, 0, 1);
    ln_rows_k<<<Ssz+1,  128>>>(wpe, nullptr, ln_p, p, 0, 1);
    qk_prep_k<<<(Hsz*Ssz*Dsz+255)/256,256>>>(p, Wq, Wk, Aq, Bk);
    colmean_part_k<<<CMCH,Dsz>>>(wte, cmP);
    colmean_red_k<<<1,Dsz>>>(cmP, cm);
    f2bf_k<<<(Vsz*Dsz/4+255)/256,256>>>(wte, wteh, Vsz*Dsz);

    // krn[h,s,t] = (Aq[h,s,:].Bk[h,t,:]) / sqrt(D) / (s+1), causal-masked  [split-2]
    mma_k<false,true,1,1,false,false,false,EPI_KRN,32><<<dim3(Ssz/128,Ssz/128,Hsz),256,smem_bytes<false,true,1,1,32>()>>>(
        Ssz,Ssz,Dsz, Aq,Bk,krn, Dsz,Dsz,Ssz,
        Hsz, 0,(ll)Ssz*Dsz, 0,(ll)Ssz*Dsz, 0,(ll)Ssz*Ssz, 1, 0, invsqD);

    zero_k<<<(Bsz*Ssz*Dsz+255)/256,256>>>(fk, Bsz*Ssz*Dsz);

    for(int it=0; it<2; it++){
        if(it==0){
            vt0_k<<<(Bsz*Ssz*Dsz+255)/256,256>>>(e, cm, Vt);
        }else{
            // fk -> bf16
            f2bf_k<<<(Bsz*Ssz*Dsz/4+255)/256,256>>>(fk, fkh, Bsz*Ssz*Dsz);
            // logits R[b,v,s] = wte[v,:] . fk[b,s,:]   [pure bf16, cp.async x4, bf16 out]
            mma_bf_k<false,true,true><<<dim3(Ssz/128,Vsz/128,Bsz),256,smem_async<false,true>()>>>(
                Vsz,Ssz,Dsz, wteh,fkh,R, Dsz,Dsz,Ssz,
                1, 0,0, (ll)Ssz*Dsz,0, (ll)Vsz*Ssz,0, 1);
            softmax_rows_bf_k<<<Bsz*Vsz,128>>>(R);
            colsum_k<<<dim3(Ssz/256,Bsz,CSCH),256>>>(R, rsP);
            // ex_wte[b,s,d] = sum_v R[b,v,s]*wte[v,d]   [pure bf16, cp.async x4, split-K=8]
            mma_bf_k<true,false,false><<<dim3(Dsz/128,Ssz/128,Bsz*KS),256,smem_async<true,false>()>>>(
                Ssz,Dsz,Vsz, R,wteh,exP, Ssz,Dsz,Dsz,
                KS, (ll)Vsz*Ssz,0, 0,0, (ll)KS*Ssz*Dsz,(ll)Ssz*Dsz, KS);
            vt1_k<<<(Bsz*Ssz*Dsz+255)/256,256>>>(e, exP, rsP, Vt);
        }
        // attn[b,s,h*D+d] = sum_t krn[h,s,t]*Vt[b,t,d]  [split-2, causal triK]
        mma_k<false,false,1,1,false,false,false,EPI_STORE,32><<<dim3(Dsz/128,Ssz/128,Bsz*Hsz),256,smem_bytes<false,false,1,1,32>()>>>(
            Ssz,Dsz,Ssz, krn,Vt,attn, Ssz,Dsz,Hsz*Dsz,
            Hsz, 0,(ll)Ssz*Ssz, (ll)Ssz*Dsz,0, (ll)Ssz*Hsz*Dsz,(ll)Dsz, 1, 1, 0.f);
        // fk += attn @ Wo[it]^T  [split-2]
        mma_k<false,true,1,1,false,false,false,EPI_ADD,32><<<dim3(Dsz/128,(Bsz*Ssz)/128,1),256,smem_bytes<false,true,1,1,32>()>>>(
            Bsz*Ssz,Dsz,Hsz*Dsz, attn, Wo+(size_t)it*Dsz*Hsz*Dsz, fk, Hsz*Dsz,Hsz*Dsz,Dsz,
            1, 0,0,0,0,0,0, 1, 0, 0.f);
        // MLP  [split-2]
        ln_rows_k<<<Bsz*Ssz,128>>>(fk, nullptr, ln_mlp, hln, 0, 1);
        mma_k<false,true,1,1,false,false,false,EPI_GELU,32><<<dim3(DFFsz/128,(Bsz*Ssz)/128,1),256,smem_bytes<false,true,1,1,32>()>>>(
            Bsz*Ssz,DFFsz,Dsz, hln,w1,act, Dsz,Dsz,DFFsz,
            1, 0,0,0,0,0,0, 1, 0, 0.f);
        mma_k<false,true,1,1,false,false,false,EPI_ADD,32><<<dim3(Dsz/128,(Bsz*Ssz)/128,1),256,smem_bytes<false,true,1,1,32>()>>>(
            Bsz*Ssz,Dsz,DFFsz, act,w2,fk, DFFsz,DFFsz,Dsz,
            1, 0,0,0,0,0,0, 1, 0, 0.f);
    }

    // final LN of last token per batch, then logits vs wte
    ln_rows_k<<<Bsz,128>>>(fk, nullptr, ln_f, oln, Ssz-1, Ssz);
    final_logits_k<<<(Vsz*32+255)/256,256>>>(oln, wte, out);
}